// round 10
// baseline (speedup 1.0000x reference)
#include <cuda_runtime.h>
#include <cuda_bf16.h>
#include <math.h>

#define NMAX 50000
#define EMAX 800000
#define DIM  128
#define HEADS 4
#define CH   32
#define EDIM 16
#define QSCALE 0.17677669529663687f   // 1/sqrt(32)

// ---------------------------------------------------------------------------
// Scratch
// ---------------------------------------------------------------------------
__device__ float g_q[NMAX * DIM];
__device__ float g_kv[(size_t)NMAX * 256];   // interleaved: k[0:128], v[128:256]
__device__ float g_xr[NMAX * DIM];
__device__ float g_h[NMAX * DIM];
__device__ float g_qwe[(size_t)NMAX * 64];
__device__ float g_qbe[NMAX * 4];
__device__ float g_eperm[(size_t)EMAX * EDIM];
__device__ int   g_src[EMAX];
__device__ int   g_dst[EMAX];
__device__ int   g_ssrc[EMAX];
__device__ int   g_eid[EMAX];
__device__ int   g_cnt[NMAX];
__device__ int   g_rowptr[NMAX + 1];
__device__ int   g_woff[NMAX];
__device__ int   g_bsum[64];
__device__ int   g_boff[64];
__device__ int   g_idx64;

// ---------------------------------------------------------------------------
// Helpers
// ---------------------------------------------------------------------------
__device__ __forceinline__ float warpSum(float v) {
#pragma unroll
    for (int off = 16; off; off >>= 1)
        v += __shfl_xor_sync(0xffffffffu, v, off);
    return v;
}

__device__ __forceinline__ float to_tf32(float x) {
    float r;
    asm("cvt.rna.tf32.f32 %0, %1;" : "=f"(r) : "f"(x));
    return r;
}

__device__ __forceinline__ void mma_tf32(float c[4],
                                         unsigned a0, unsigned a1, unsigned a2, unsigned a3,
                                         unsigned b0, unsigned b1) {
    asm volatile(
        "mma.sync.aligned.m16n8k8.row.col.f32.tf32.tf32.f32 "
        "{%0,%1,%2,%3},{%4,%5,%6,%7},{%8,%9},{%0,%1,%2,%3};"
        : "+f"(c[0]), "+f"(c[1]), "+f"(c[2]), "+f"(c[3])
        : "r"(a0), "r"(a1), "r"(a2), "r"(a3), "r"(b0), "r"(b1));
}

// ---------------------------------------------------------------------------
// Index detect (parallel) / convert (+fused histogram)
// ---------------------------------------------------------------------------
__global__ void detect_idx_kernel(const int* raw) {
    int t = threadIdx.x;   // 32 threads
    int hi_nz = 0, lo_nz = 0;
    for (int i = t; i < 256; i += 32) {
        if (raw[2 * i + 1] != 0) hi_nz = 1;
        if (raw[2 * i] != 0) lo_nz = 1;
    }
    unsigned hi = __ballot_sync(0xffffffffu, hi_nz);
    unsigned lo = __ballot_sync(0xffffffffu, lo_nz);
    if (t == 0) g_idx64 = (hi == 0u && lo != 0u) ? 1 : 0;
}

__global__ void zero_cnt_kernel(int N) {
    int i = blockIdx.x * blockDim.x + threadIdx.x;
    if (i < N) g_cnt[i] = 0;
}

__global__ void convert_idx_kernel(const void* raw, int E) {
    int i = blockIdx.x * blockDim.x + threadIdx.x;
    if (i >= E) return;
    int s, d;
    if (g_idx64) {
        const long long* p = (const long long*)raw;
        s = (int)p[i];
        d = (int)p[E + i];
    } else {
        const int* p = (const int*)raw;
        s = p[i];
        d = p[E + i];
    }
    g_src[i] = s;
    g_dst[i] = d;
    atomicAdd(&g_cnt[d], 1);
}

// ---------------------------------------------------------------------------
// 3-phase exclusive scan
// ---------------------------------------------------------------------------
__global__ void __launch_bounds__(1024)
scanA_kernel(int N) {
    __shared__ int wsum[32];
    int t = threadIdx.x;
    int i = blockIdx.x * 1024 + t;
    int v = (i < N) ? g_cnt[i] : 0;
    int inc = v;
#pragma unroll
    for (int off = 1; off < 32; off <<= 1) {
        int u = __shfl_up_sync(0xffffffffu, inc, off);
        if ((t & 31) >= off) inc += u;
    }
    if ((t & 31) == 31) wsum[t >> 5] = inc;
    __syncthreads();
    if (t < 32) {
        int w = wsum[t];
        int wi = w;
#pragma unroll
        for (int off = 1; off < 32; off <<= 1) {
            int u = __shfl_up_sync(0xffffffffu, wi, off);
            if (t >= off) wi += u;
        }
        wsum[t] = wi - w;
    }
    __syncthreads();
    int exc = inc - v + wsum[t >> 5];
    if (i < N) g_rowptr[i] = exc;
    if (t == 1023) g_bsum[blockIdx.x] = exc + v;
}

__global__ void scanB_kernel(int nb, int N, int E) {
    int lane = threadIdx.x;
    int v0 = (lane < nb) ? g_bsum[lane] : 0;
    int v1 = (32 + lane < nb) ? g_bsum[32 + lane] : 0;
    int i0 = v0, i1 = v1;
#pragma unroll
    for (int off = 1; off < 32; off <<= 1) {
        int u = __shfl_up_sync(0xffffffffu, i0, off);
        if (lane >= off) i0 += u;
        int u2 = __shfl_up_sync(0xffffffffu, i1, off);
        if (lane >= off) i1 += u2;
    }
    int tot0 = __shfl_sync(0xffffffffu, i0, 31);
    i1 += tot0;
    g_boff[lane] = i0 - v0;
    g_boff[32 + lane] = i1 - v1;
    if (lane == 0) g_rowptr[N] = E;
}

__global__ void __launch_bounds__(1024)
scanC_kernel(int N) {
    int i = blockIdx.x * 1024 + threadIdx.x;
    if (i < N) {
        int r = g_rowptr[i] + g_boff[blockIdx.x];
        g_rowptr[i] = r;
        g_woff[i] = r;
    }
}

__global__ void scatter_kernel(int E) {
    int i = blockIdx.x * blockDim.x + threadIdx.x;
    if (i >= E) return;
    int d = g_dst[i];
    int pos = atomicAdd(&g_woff[d], 1);
    g_ssrc[pos] = g_src[i];
    g_eid[pos] = i;
}

__global__ void __launch_bounds__(256)
permute_eattr_kernel(const float* __restrict__ eattr, int E) {
    int i = blockIdx.x * blockDim.x + threadIdx.x;
    if (i >= E * 4) return;
    int p = i >> 2, q = (i & 3) * 4;
    int e = g_eid[p];
    *(float4*)&g_eperm[(size_t)p * EDIM + q] =
        *(const float4*)&eattr[(size_t)e * EDIM + q];
}

// ---------------------------------------------------------------------------
// TF32 MMA core: BK=16, double-buffered smem, ONE sync per k-tile.
// ---------------------------------------------------------------------------
__device__ __forceinline__ void mma_core(
    const float* __restrict__ A, const float* __restrict__ B,
    int M, int K, int Nout, int n_base, int m0,
    float (&acc)[2][8][4], float (&As)[2][128][20], float (&Bs)[2][16][136])
{
    const int tid = threadIdx.x;
    const int lane = tid & 31;
    const int wid = tid >> 5;
    const int warp_m = wid & 3;
    const int warp_n = wid >> 2;

#pragma unroll
    for (int i = 0; i < 2; i++)
#pragma unroll
        for (int j = 0; j < 8; j++)
#pragma unroll
            for (int c = 0; c < 4; c++) acc[i][j][c] = 0.f;

    float4 pa[2], pb[2];

#define LOAD_TILE(K0)                                                         \
    {                                                                         \
        const int k0c_ = (K0);                                                \
        _Pragma("unroll")                                                     \
        for (int _t = 0; _t < 2; _t++) {                                      \
            int j = tid + _t * 256;                                           \
            int r = j >> 2, q = (j & 3) * 4;                                  \
            pa[_t] = (m0 + r < M)                                             \
                ? *(const float4*)&A[(size_t)(m0 + r) * K + k0c_ + q]         \
                : make_float4(0.f, 0.f, 0.f, 0.f);                            \
            int br = j >> 5, c4 = (j & 31) * 4;                               \
            pb[_t] = *(const float4*)&B[(size_t)(k0c_ + br) * Nout + n_base + c4]; \
        }                                                                     \
    }

#define STORE_TILE(BUF)                                                       \
    {                                                                         \
        const int buf_ = (BUF);                                               \
        _Pragma("unroll")                                                     \
        for (int _t = 0; _t < 2; _t++) {                                      \
            int j = tid + _t * 256;                                           \
            int r = j >> 2, q = (j & 3) * 4;                                  \
            As[buf_][r][q + 0] = to_tf32(pa[_t].x);                           \
            As[buf_][r][q + 1] = to_tf32(pa[_t].y);                           \
            As[buf_][r][q + 2] = to_tf32(pa[_t].z);                           \
            As[buf_][r][q + 3] = to_tf32(pa[_t].w);                           \
            int br = j >> 5, c4 = (j & 31) * 4;                               \
            Bs[buf_][br][c4 + 0] = to_tf32(pb[_t].x);                         \
            Bs[buf_][br][c4 + 1] = to_tf32(pb[_t].y);                         \
            Bs[buf_][br][c4 + 2] = to_tf32(pb[_t].z);                         \
            Bs[buf_][br][c4 + 3] = to_tf32(pb[_t].w);                         \
        }                                                                     \
    }

    LOAD_TILE(0);
    STORE_TILE(0);
    __syncthreads();

    const int T = K >> 4;
#pragma unroll 2
    for (int t = 0; t < T; t++) {
        if (t + 1 < T) LOAD_TILE((t + 1) << 4);
        const int b = t & 1;
#pragma unroll
        for (int kk = 0; kk < 16; kk += 8) {
            unsigned bf[8][2];
#pragma unroll
            for (int nt = 0; nt < 8; nt++) {
                int n = warp_n * 64 + nt * 8 + (lane >> 2);
                bf[nt][0] = __float_as_uint(Bs[b][kk + (lane & 3)][n]);
                bf[nt][1] = __float_as_uint(Bs[b][kk + 4 + (lane & 3)][n]);
            }
#pragma unroll
            for (int mt = 0; mt < 2; mt++) {
                int r0 = warp_m * 32 + mt * 16 + (lane >> 2);
                unsigned a0 = __float_as_uint(As[b][r0][kk + (lane & 3)]);
                unsigned a1 = __float_as_uint(As[b][r0 + 8][kk + (lane & 3)]);
                unsigned a2 = __float_as_uint(As[b][r0][kk + 4 + (lane & 3)]);
                unsigned a3 = __float_as_uint(As[b][r0 + 8][kk + 4 + (lane & 3)]);
#pragma unroll
                for (int nt = 0; nt < 8; nt++)
                    mma_tf32(acc[mt][nt], a0, a1, a2, a3, bf[nt][0], bf[nt][1]);
            }
        }
        if (t + 1 < T) STORE_TILE((t + 1) & 1);
        __syncthreads();
    }
#undef LOAD_TILE
#undef STORE_TILE
}

// ---------------------------------------------------------------------------
// proj4 (q/k/v/skip). k,v go interleaved into g_kv; q scaled at store.
// ---------------------------------------------------------------------------
__global__ void __launch_bounds__(256)
proj_mma_kernel(const float* __restrict__ A,
                const float* __restrict__ Wq, const float* __restrict__ bq,
                const float* __restrict__ Wk, const float* __restrict__ bk,
                const float* __restrict__ Wv, const float* __restrict__ bv,
                const float* __restrict__ Ws, const float* __restrict__ bs,
                int M)
{
    const float* B; const float* bias; float* C; float scale; int cst;
    switch (blockIdx.y) {
        case 0: B = Wq; bias = bq; C = g_q;        scale = QSCALE; cst = 128; break;
        case 1: B = Wk; bias = bk; C = g_kv;       scale = 1.f;    cst = 256; break;
        case 2: B = Wv; bias = bv; C = g_kv + 128; scale = 1.f;    cst = 256; break;
        default: B = Ws; bias = bs; C = g_xr;      scale = 1.f;    cst = 128; break;
    }
    __shared__ float As[2][128][20];
    __shared__ float Bs[2][16][136];
    float acc[2][8][4];
    const int m0 = blockIdx.x * 128;
    mma_core(A, B, M, DIM, DIM, 0, m0, acc, As, Bs);

    const int lane = threadIdx.x & 31;
    const int wid = threadIdx.x >> 5;
    const int warp_m = wid & 3, warp_n = wid >> 2;
#pragma unroll
    for (int mt = 0; mt < 2; mt++)
#pragma unroll
        for (int h2 = 0; h2 < 2; h2++) {
            int m = m0 + warp_m * 32 + mt * 16 + (lane >> 2) + h2 * 8;
            if (m >= M) continue;
#pragma unroll
            for (int nt = 0; nt < 8; nt++) {
                int col = warp_n * 64 + nt * 8 + (lane & 3) * 2;
                float2 st;
                st.x = (acc[mt][nt][h2 * 2]     + __ldg(&bias[col]))     * scale;
                st.y = (acc[mt][nt][h2 * 2 + 1] + __ldg(&bias[col + 1])) * scale;
                *(float2*)&C[(size_t)m * cst + col] = st;
            }
        }
}

// ---------------------------------------------------------------------------
// Fused FFN: out = LN( h + relu(h@Wf1+bf1)@Wf2 + bf2 ; g2,b2 )
// ---------------------------------------------------------------------------
#define FFN_SMEM_FLOATS (2 * 128 * 132 + 2 * 16 * 136)

__global__ void __launch_bounds__(256)
ffn_fused_kernel(const float* __restrict__ A, const float* __restrict__ Wf1,
                 const float* __restrict__ bf1, const float* __restrict__ Wf2,
                 const float* __restrict__ bf2, float* __restrict__ C,
                 const float* __restrict__ gamma, const float* __restrict__ betap,
                 int M)
{
    extern __shared__ float sm[];
    float (*H)[132] = (float(*)[132])sm;
    float (*T)[132] = (float(*)[132])(sm + 128 * 132);
    float (*Bs)[16][136] = (float(*)[16][136])(sm + 2 * 128 * 132);

    const int tid = threadIdx.x;
    const int lane = tid & 31;
    const int wid = tid >> 5;
    const int warp_m = wid & 3;
    const int warp_n = wid >> 2;
    const int m0 = blockIdx.x * 128;

#pragma unroll
    for (int t = 0; t < 16; t++) {
        int j = tid + t * 256;
        int r = j >> 5, c4 = (j & 31) * 4;
        float4 v = (m0 + r < M) ? *(const float4*)&A[(size_t)(m0 + r) * DIM + c4]
                                : make_float4(0.f, 0.f, 0.f, 0.f);
        H[r][c4 + 0] = to_tf32(v.x);
        H[r][c4 + 1] = to_tf32(v.y);
        H[r][c4 + 2] = to_tf32(v.z);
        H[r][c4 + 3] = to_tf32(v.w);
    }
    __syncthreads();

    float acc2[2][8][4];
#pragma unroll
    for (int i = 0; i < 2; i++)
#pragma unroll
        for (int j = 0; j < 8; j++)
#pragma unroll
            for (int c = 0; c < 4; c++) acc2[i][j][c] = 0.f;

    float4 pbv[2];

#define LOADB1(CH_, T0)                                                       \
    {                                                                         \
        _Pragma("unroll")                                                     \
        for (int _t = 0; _t < 2; _t++) {                                      \
            int j = tid + _t * 256;                                           \
            int br = j >> 5, c4 = (j & 31) * 4;                               \
            pbv[_t] = *(const float4*)&Wf1[(size_t)((T0) * 16 + br) * 512     \
                                           + (CH_) * 128 + c4];               \
        }                                                                     \
    }
#define LOADB2(CH_, T0)                                                       \
    {                                                                         \
        _Pragma("unroll")                                                     \
        for (int _t = 0; _t < 2; _t++) {                                      \
            int j = tid + _t * 256;                                           \
            int br = j >> 5, c4 = (j & 31) * 4;                               \
            pbv[_t] = *(const float4*)&Wf2[(size_t)((CH_) * 128 + (T0) * 16 + br) * 128 + c4]; \
        }                                                                     \
    }
#define STOREB(BUF)                                                           \
    {                                                                         \
        const int buf_ = (BUF);                                               \
        _Pragma("unroll")                                                     \
        for (int _t = 0; _t < 2; _t++) {                                      \
            int j = tid + _t * 256;                                           \
            int br = j >> 5, c4 = (j & 31) * 4;                               \
            Bs[buf_][br][c4 + 0] = to_tf32(pbv[_t].x);                        \
            Bs[buf_][br][c4 + 1] = to_tf32(pbv[_t].y);                        \
            Bs[buf_][br][c4 + 2] = to_tf32(pbv[_t].z);                        \
            Bs[buf_][br][c4 + 3] = to_tf32(pbv[_t].w);                        \
        }                                                                     \
    }

#define GEMM_STEP(ACC, ASRC, B_, KGLOB)                                       \
    {                                                                         \
        _Pragma("unroll")                                                     \
        for (int kk0 = 0; kk0 < 16; kk0 += 8) {                               \
            int kk = (KGLOB) + kk0;                                           \
            unsigned bf[8][2];                                                \
            _Pragma("unroll")                                                 \
            for (int nt = 0; nt < 8; nt++) {                                  \
                int n = warp_n * 64 + nt * 8 + (lane >> 2);                   \
                bf[nt][0] = __float_as_uint(Bs[B_][kk0 + (lane & 3)][n]);     \
                bf[nt][1] = __float_as_uint(Bs[B_][kk0 + 4 + (lane & 3)][n]); \
            }                                                                 \
            _Pragma("unroll")                                                 \
            for (int mt = 0; mt < 2; mt++) {                                  \
                int r0 = warp_m * 32 + mt * 16 + (lane >> 2);                 \
                unsigned a0 = __float_as_uint(ASRC[r0][kk + (lane & 3)]);     \
                unsigned a1 = __float_as_uint(ASRC[r0 + 8][kk + (lane & 3)]); \
                unsigned a2 = __float_as_uint(ASRC[r0][kk + 4 + (lane & 3)]); \
                unsigned a3 = __float_as_uint(ASRC[r0 + 8][kk + 4 + (lane & 3)]); \
                _Pragma("unroll")                                             \
                for (int nt = 0; nt < 8; nt++)                                \
                    mma_tf32(ACC[mt][nt], a0, a1, a2, a3, bf[nt][0], bf[nt][1]); \
            }                                                                 \
        }                                                                     \
    }

#pragma unroll 1
    for (int c = 0; c < 4; c++) {
        float acc1[2][8][4];
#pragma unroll
        for (int i = 0; i < 2; i++)
#pragma unroll
            for (int j = 0; j < 8; j++)
#pragma unroll
                for (int cc = 0; cc < 4; cc++) acc1[i][j][cc] = 0.f;

        LOADB1(c, 0);
        STOREB(0);
        __syncthreads();
#pragma unroll
        for (int t = 0; t < 8; t++) {
            if (t < 7) LOADB1(c, t + 1);
            GEMM_STEP(acc1, H, t & 1, t * 16);
            if (t < 7) STOREB((t + 1) & 1);
            __syncthreads();
        }

#pragma unroll
        for (int mt = 0; mt < 2; mt++)
#pragma unroll
            for (int h2 = 0; h2 < 2; h2++) {
                int row = warp_m * 32 + mt * 16 + (lane >> 2) + h2 * 8;
#pragma unroll
                for (int nt = 0; nt < 8; nt++) {
                    int col = warp_n * 64 + nt * 8 + (lane & 3) * 2;
                    int gcol = c * 128 + col;
                    float t0 = fmaxf(acc1[mt][nt][h2 * 2]     + __ldg(&bf1[gcol]), 0.f);
                    float t1 = fmaxf(acc1[mt][nt][h2 * 2 + 1] + __ldg(&bf1[gcol + 1]), 0.f);
                    T[row][col]     = to_tf32(t0);
                    T[row][col + 1] = to_tf32(t1);
                }
            }

        LOADB2(c, 0);
        STOREB(0);
        __syncthreads();
#pragma unroll
        for (int t = 0; t < 8; t++) {
            if (t < 7) LOADB2(c, t + 1);
            GEMM_STEP(acc2, T, t & 1, t * 16);
            if (t < 7) STOREB((t + 1) & 1);
            __syncthreads();
        }
    }
#undef LOADB1
#undef LOADB2
#undef STOREB
#undef GEMM_STEP

    float (*pr)[2] = (float(*)[2])H;
    float mu[2][2];
#pragma unroll
    for (int mt = 0; mt < 2; mt++)
#pragma unroll
        for (int h2 = 0; h2 < 2; h2++) {
            int row = warp_m * 32 + mt * 16 + (lane >> 2) + h2 * 8;
            int m = m0 + row;
            float s = 0.f;
#pragma unroll
            for (int nt = 0; nt < 8; nt++) {
                int col = warp_n * 64 + nt * 8 + (lane & 3) * 2;
                float r0 = (m < M) ? __ldg(&A[(size_t)m * DIM + col])     : 0.f;
                float r1 = (m < M) ? __ldg(&A[(size_t)m * DIM + col + 1]) : 0.f;
                float t0 = acc2[mt][nt][h2 * 2]     + __ldg(&bf2[col])     + r0;
                float t1 = acc2[mt][nt][h2 * 2 + 1] + __ldg(&bf2[col + 1]) + r1;
                acc2[mt][nt][h2 * 2] = t0;
                acc2[mt][nt][h2 * 2 + 1] = t1;
                s += t0 + t1;
            }
            s += __shfl_xor_sync(0xffffffffu, s, 1);
            s += __shfl_xor_sync(0xffffffffu, s, 2);
            if ((lane & 3) == 0) pr[row][warp_n] = s;
        }
    __syncthreads();
#pragma unroll
    for (int mt = 0; mt < 2; mt++)
#pragma unroll
        for (int h2 = 0; h2 < 2; h2++) {
            int row = warp_m * 32 + mt * 16 + (lane >> 2) + h2 * 8;
            mu[mt][h2] = (pr[row][0] + pr[row][1]) * (1.0f / 128.0f);
        }
    __syncthreads();
#pragma unroll
    for (int mt = 0; mt < 2; mt++)
#pragma unroll
        for (int h2 = 0; h2 < 2; h2++) {
            int row = warp_m * 32 + mt * 16 + (lane >> 2) + h2 * 8;
            float vs = 0.f;
#pragma unroll
            for (int nt = 0; nt < 8; nt++) {
                float d0 = acc2[mt][nt][h2 * 2]     - mu[mt][h2];
                float d1 = acc2[mt][nt][h2 * 2 + 1] - mu[mt][h2];
                vs += d0 * d0 + d1 * d1;
            }
            vs += __shfl_xor_sync(0xffffffffu, vs, 1);
            vs += __shfl_xor_sync(0xffffffffu, vs, 2);
            if ((lane & 3) == 0) pr[row][warp_n] = vs;
        }
    __syncthreads();
#pragma unroll
    for (int mt = 0; mt < 2; mt++)
#pragma unroll
        for (int h2 = 0; h2 < 2; h2++) {
            int row = warp_m * 32 + mt * 16 + (lane >> 2) + h2 * 8;
            int m = m0 + row;
            if (m >= M) continue;
            float var = (pr[row][0] + pr[row][1]) * (1.0f / 128.0f);
            float inv = rsqrtf(var + 1e-5f);
#pragma unroll
            for (int nt = 0; nt < 8; nt++) {
                int col = warp_n * 64 + nt * 8 + (lane & 3) * 2;
                float2 st;
                st.x = (acc2[mt][nt][h2 * 2]     - mu[mt][h2]) * inv * __ldg(&gamma[col])     + __ldg(&betap[col]);
                st.y = (acc2[mt][nt][h2 * 2 + 1] - mu[mt][h2]) * inv * __ldg(&gamma[col + 1]) + __ldg(&betap[col + 1]);
                *(float2*)&C[(size_t)m * DIM + col] = st;
            }
        }
}

// ---------------------------------------------------------------------------
// qwe precompute
// ---------------------------------------------------------------------------
__global__ void __launch_bounds__(256)
qwe_kernel(const float* __restrict__ We, const float* __restrict__ be, int N)
{
    __shared__ float sWe[EDIM * DIM];
    __shared__ float sq[4][DIM];
    __shared__ float sbe[DIM];
    int tid = threadIdx.x;
    for (int i = tid; i < EDIM * DIM; i += 256) sWe[i] = We[i];
    if (tid < DIM) sbe[tid] = be[tid];
    int n0 = blockIdx.x * 4;
    for (int i = tid; i < 4 * DIM; i += 256) {
        int nn = i >> 7, c = i & 127;
        sq[nn][c] = (n0 + nn < N) ? g_q[(size_t)(n0 + nn) * DIM + c] : 0.f;
    }
    __syncthreads();
    int nn = tid >> 6, r = tid & 63, h = r >> 4, i = r & 15;
    int n = n0 + nn;
    if (n >= N) return;
    float a = 0.f;
#pragma unroll
    for (int c = 0; c < 32; c++)
        a = fmaf(sq[nn][h * 32 + c], sWe[i * DIM + h * 32 + c], a);
    g_qwe[(size_t)n * 64 + h * 16 + i] = a;
    if (i == 0) {
        float qb = 0.f;
#pragma unroll
        for (int c = 0; c < 32; c++)
            qb = fmaf(sq[nn][h * 32 + c], sbe[h * 32 + c], qb);
        g_qbe[n * 4 + h] = qb;
    }
}

// ---------------------------------------------------------------------------
// Warp-per-node attention, 4-edge pipeline, interleaved k/v rows.
// ---------------------------------------------------------------------------
__global__ void __launch_bounds__(256)
node_attn_kernel(const float* __restrict__ We, const float* __restrict__ be,
                 const float* __restrict__ x,  const float* __restrict__ Wbeta,
                 const float* __restrict__ g1, const float* __restrict__ b1,
                 int N)
{
    __shared__ float sWe[EDIM][DIM];
    __shared__ float sbe[DIM];
    for (int i = threadIdx.x; i < EDIM * DIM; i += 256)
        ((float*)sWe)[i] = We[i];
    if (threadIdx.x < DIM) sbe[threadIdx.x] = be[threadIdx.x];
    __syncthreads();

    const int lane = threadIdx.x & 31;
    const int g = lane >> 3;
    const int l8 = lane & 7;
    const int ch0 = g * 32 + l8 * 4;
    const int warp = blockIdx.x * (blockDim.x >> 5) + (threadIdx.x >> 5);
    const int nwarps = gridDim.x * (blockDim.x >> 5);

    for (int n = warp; n < N; n += nwarps) {
        float4 q4 = *(const float4*)&g_q[(size_t)n * DIM + ch0];
        float2 qwe2 = *(const float2*)&g_qwe[(size_t)n * 64 + g * 16 + 2 * l8];
        float qbe = g_qbe[n * 4 + g];

        float4 acc = make_float4(0.f, 0.f, 0.f, 0.f);
        float s0 = 0.f, s1 = 0.f, den = 0.f;

        int beg = g_rowptr[n], end = g_rowptr[n + 1];
        int p = beg;
        for (; p + 4 <= end; p += 4) {
            int sA = __ldg(&g_ssrc[p]);
            int sB = __ldg(&g_ssrc[p + 1]);
            int sC = __ldg(&g_ssrc[p + 2]);
            int sD = __ldg(&g_ssrc[p + 3]);
            const float* rA = g_kv + (size_t)sA * 256 + ch0;
            const float* rB = g_kv + (size_t)sB * 256 + ch0;
            const float* rC = g_kv + (size_t)sC * 256 + ch0;
            const float* rD = g_kv + (size_t)sD * 256 + ch0;
            float4 kA = *(const float4*)rA;
            float4 kB = *(const float4*)rB;
            float4 kC = *(const float4*)rC;
            float4 kD = *(const float4*)rD;
            float4 vA = *(const float4*)(rA + 128);
            float4 vB = *(const float4*)(rB + 128);
            float4 vC = *(const float4*)(rC + 128);
            float4 vD = *(const float4*)(rD + 128);
            float2 aA = *(const float2*)&g_eperm[(size_t)p * EDIM + 2 * l8];
            float2 aB = *(const float2*)&g_eperm[(size_t)(p + 1) * EDIM + 2 * l8];
            float2 aC = *(const float2*)&g_eperm[(size_t)(p + 2) * EDIM + 2 * l8];
            float2 aD = *(const float2*)&g_eperm[(size_t)(p + 3) * EDIM + 2 * l8];

            float pA = q4.x * kA.x + q4.y * kA.y + q4.z * kA.z + q4.w * kA.w
                     + aA.x * qwe2.x + aA.y * qwe2.y;
            float pB = q4.x * kB.x + q4.y * kB.y + q4.z * kB.z + q4.w * kB.w
                     + aB.x * qwe2.x + aB.y * qwe2.y;
            float pC = q4.x * kC.x + q4.y * kC.y + q4.z * kC.z + q4.w * kC.w
                     + aC.x * qwe2.x + aC.y * qwe2.y;
            float pD = q4.x * kD.x + q4.y * kD.y + q4.z * kD.z + q4.w * kD.w
                     + aD.x * qwe2.x + aD.y * qwe2.y;
            pA += __shfl_xor_sync(0xffffffffu, pA, 1);
            pB += __shfl_xor_sync(0xffffffffu, pB, 1);
            pC += __shfl_xor_sync(0xffffffffu, pC, 1);
            pD += __shfl_xor_sync(0xffffffffu, pD, 1);
            pA += __shfl_xor_sync(0xffffffffu, pA, 2);
            pB += __shfl_xor_sync(0xffffffffu, pB, 2);
            pC += __shfl_xor_sync(0xffffffffu, pC, 2);
            pD += __shfl_xor_sync(0xffffffffu, pD, 2);
            pA += __shfl_xor_sync(0xffffffffu, pA, 4);
            pB += __shfl_xor_sync(0xffffffffu, pB, 4);
            pC += __shfl_xor_sync(0xffffffffu, pC, 4);
            pD += __shfl_xor_sync(0xffffffffu, pD, 4);
            float eA = __expf(pA + qbe);
            float eB = __expf(pB + qbe);
            float eC = __expf(pC + qbe);
            float eD = __expf(pD + qbe);
            den += eA;
            acc.x = fmaf(eA, vA.x, acc.x); acc.y = fmaf(eA, vA.y, acc.y);
            acc.z = fmaf(eA, vA.z, acc.z); acc.w = fmaf(eA, vA.w, acc.w);
            s0 = fmaf(eA, aA.x, s0); s1 = fmaf(eA, aA.y, s1);
            den += eB;
            acc.x = fmaf(eB, vB.x, acc.x); acc.y = fmaf(eB, vB.y, acc.y);
            acc.z = fmaf(eB, vB.z, acc.z); acc.w = fmaf(eB, vB.w, acc.w);
            s0 = fmaf(eB, aB.x, s0); s1 = fmaf(eB, aB.y, s1);
            den += eC;
            acc.x = fmaf(eC, vC.x, acc.x); acc.y = fmaf(eC, vC.y, acc.y);
            acc.z = fmaf(eC, vC.z, acc.z); acc.w = fmaf(eC, vC.w, acc.w);
            s0 = fmaf(eC, aC.x, s0); s1 = fmaf(eC, aC.y, s1);
            den += eD;
            acc.x = fmaf(eD, vD.x, acc.x); acc.y = fmaf(eD, vD.y, acc.y);
            acc.z = fmaf(eD, vD.z, acc.z); acc.w = fmaf(eD, vD.w, acc.w);
            s0 = fmaf(eD, aD.x, s0); s1 = fmaf(eD, aD.y, s1);
        }
        for (; p < end; p++) {
            int sA = __ldg(&g_ssrc[p]);
            float2 aA = *(const float2*)&g_eperm[(size_t)p * EDIM + 2 * l8];
            const float* rA = g_kv + (size_t)sA * 256 + ch0;
            float4 kA = *(const float4*)rA;
            float4 vA = *(const float4*)(rA + 128);
            float pp = q4.x * kA.x + q4.y * kA.y + q4.z * kA.z + q4.w * kA.w
                     + aA.x * qwe2.x + aA.y * qwe2.y;
            pp += __shfl_xor_sync(0xffffffffu, pp, 1);
            pp += __shfl_xor_sync(0xffffffffu, pp, 2);
            pp += __shfl_xor_sync(0xffffffffu, pp, 4);
            float ea = __expf(pp + qbe);
            den += ea;
            acc.x = fmaf(ea, vA.x, acc.x); acc.y = fmaf(ea, vA.y, acc.y);
            acc.z = fmaf(ea, vA.z, acc.z); acc.w = fmaf(ea, vA.w, acc.w);
            s0 = fmaf(ea, aA.x, s0); s1 = fmaf(ea, aA.y, s1);
        }

        float4 ev;
        ev.x = den * sbe[ch0];
        ev.y = den * sbe[ch0 + 1];
        ev.z = den * sbe[ch0 + 2];
        ev.w = den * sbe[ch0 + 3];
#pragma unroll
        for (int jj = 0; jj < 8; jj++) {
            int srcl = (g << 3) | jj;
            float sj0 = __shfl_sync(0xffffffffu, s0, srcl);
            float sj1 = __shfl_sync(0xffffffffu, s1, srcl);
            float4 w0 = *(const float4*)&sWe[2 * jj][ch0];
            float4 w1 = *(const float4*)&sWe[2 * jj + 1][ch0];
            ev.x += sj0 * w0.x + sj1 * w1.x;
            ev.y += sj0 * w0.y + sj1 * w1.y;
            ev.z += sj0 * w0.z + sj1 * w1.z;
            ev.w += sj0 * w0.w + sj1 * w1.w;
        }
        float rden = 1.0f / (den + 1e-16f);
        float o[4] = {(acc.x + ev.x) * rden, (acc.y + ev.y) * rden,
                      (acc.z + ev.z) * rden, (acc.w + ev.w) * rden};

        float4 xr4 = *(const float4*)&g_xr[(size_t)n * DIM + ch0];
        float4 wb0 = *(const float4*)&Wbeta[ch0];
        float4 wb1 = *(const float4*)&Wbeta[DIM + ch0];
        float4 wb2 = *(const float4*)&Wbeta[2 * DIM + ch0];
        float xr[4] = {xr4.x, xr4.y, xr4.z, xr4.w};
        float z = wb0.x * o[0] + wb1.x * xr[0] + wb2.x * (o[0] - xr[0])
                + wb0.y * o[1] + wb1.y * xr[1] + wb2.y * (o[1] - xr[1])
                + wb0.z * o[2] + wb1.z * xr[2] + wb2.z * (o[2] - xr[2])
                + wb0.w * o[3] + wb1.w * xr[3] + wb2.w * (o[3] - xr[3]);
        z = warpSum(z);
        float beta = 1.0f / (1.0f + __expf(-z));

        float4 xv = *(const float4*)&x[(size_t)n * DIM + ch0];
        float xx[4] = {xv.x, xv.y, xv.z, xv.w};
        float tv[4], ts = 0.f;
#pragma unroll
        for (int c = 0; c < 4; c++) {
            tv[c] = xx[c] + beta * xr[c] + (1.0f - beta) * o[c];
            ts += tv[c];
        }
        float mu = warpSum(ts) * (1.0f / 128.0f);
        float vs = 0.f;
#pragma unroll
        for (int c = 0; c < 4; c++) { tv[c] -= mu; vs += tv[c] * tv[c]; }
        float var = warpSum(vs) * (1.0f / 128.0f);
        float inv = rsqrtf(var + 1e-5f);

        float4 gg = *(const float4*)&g1[ch0];
        float4 bb = *(const float4*)&b1[ch0];
        float4 st;
        st.x = tv[0] * inv * gg.x + bb.x;
        st.y = tv[1] * inv * gg.y + bb.y;
        st.z = tv[2] * inv * gg.z + bb.z;
        st.w = tv[3] * inv * gg.w + bb.w;
        *(float4*)&g_h[(size_t)n * DIM + ch0] = st;
    }
}

// ---------------------------------------------------------------------------
// Launch (fork-join streams: CSR chain || projections; fused FFN)
// ---------------------------------------------------------------------------
extern "C" void kernel_launch(void* const* d_in, const int* in_sizes, int n_in,
                              void* d_out, int out_size)
{
    const float* x      = (const float*)d_in[0];
    const void*  eidx   = d_in[1];
    const float* eattr  = (const float*)d_in[2];
    const float* Wq     = (const float*)d_in[3];
    const float* bq     = (const float*)d_in[4];
    const float* Wk     = (const float*)d_in[5];
    const float* bk     = (const float*)d_in[6];
    const float* Wv     = (const float*)d_in[7];
    const float* bv     = (const float*)d_in[8];
    const float* We     = (const float*)d_in[9];
    const float* be     = (const float*)d_in[10];
    const float* Ws     = (const float*)d_in[11];
    const float* bs     = (const float*)d_in[12];
    const float* Wbeta  = (const float*)d_in[13];
    const float* g1     = (const float*)d_in[14];
    const float* b1     = (const float*)d_in[15];
    const float* Wf1    = (const float*)d_in[16];
    const float* bf1    = (const float*)d_in[17];
    const float* Wf2    = (const float*)d_in[18];
    const float* bf2    = (const float*)d_in[19];
    const float* g2     = (const float*)d_in[20];
    const float* b2     = (const float*)d_in[21];

    const int N = in_sizes[0] / DIM;
    const int E = in_sizes[1] / 2;

    float* h;
    cudaGetSymbolAddress((void**)&h, g_h);

    static cudaStream_t s1 = nullptr;
    static cudaEvent_t evFork = nullptr, evCsr = nullptr;
    if (!s1) {
        cudaStreamCreate(&s1);
        cudaEventCreateWithFlags(&evFork, cudaEventDisableTiming);
        cudaEventCreateWithFlags(&evCsr, cudaEventDisableTiming);
        cudaFuncSetAttribute(ffn_fused_kernel,
                             cudaFuncAttributeMaxDynamicSharedMemorySize,
                             FFN_SMEM_FLOATS * 4);
    }

    const int nb = (N + 1023) / 1024;
    const int gm = (N + 127) / 128;

    // fork
    cudaEventRecord(evFork, 0);
    cudaStreamWaitEvent(s1, evFork, 0);

    // CSR chain on s1
    detect_idx_kernel<<<1, 32, 0, s1>>>((const int*)eidx);
    zero_cnt_kernel<<<(N + 255) / 256, 256, 0, s1>>>(N);
    convert_idx_kernel<<<(E + 255) / 256, 256, 0, s1>>>(eidx, E);
    scanA_kernel<<<nb, 1024, 0, s1>>>(N);
    scanB_kernel<<<1, 32, 0, s1>>>(nb, N, E);
    scanC_kernel<<<nb, 1024, 0, s1>>>(N);
    scatter_kernel<<<(E + 255) / 256, 256, 0, s1>>>(E);
    permute_eattr_kernel<<<(E * 4 + 255) / 256, 256, 0, s1>>>(eattr, E);
    cudaEventRecord(evCsr, s1);

    // projections + qwe on default stream
    dim3 gproj(gm, 4);
    proj_mma_kernel<<<gproj, 256>>>(x, Wq, bq, Wk, bk, Wv, bv, Ws, bs, N);
    qwe_kernel<<<(N + 3) / 4, 256>>>(We, be, N);

    // join
    cudaStreamWaitEvent(0, evCsr, 0);

    node_attn_kernel<<<1184, 256>>>(We, be, x, Wbeta, g1, b1, N);

    // fused FFN + residual + LN2
    ffn_fused_kernel<<<gm, 256, FFN_SMEM_FLOATS * 4>>>(
        h, Wf1, bf1, Wf2, bf2, (float*)d_out, g2, b2, N);
}

// round 11
// speedup vs baseline: 1.0614x; 1.0614x over previous
#include <cuda_runtime.h>
#include <cuda_bf16.h>
#include <math.h>

#define NMAX 50000
#define EMAX 800000
#define DIM  128
#define HEADS 4
#define CH   32
#define EDIM 16
#define QSCALE 0.17677669529663687f   // 1/sqrt(32)

// ---------------------------------------------------------------------------
// Scratch
// ---------------------------------------------------------------------------
__device__ float g_q[NMAX * DIM];
__device__ float g_k[NMAX * DIM];
__device__ float g_v[NMAX * DIM];
__device__ float g_xr[NMAX * DIM];
__device__ float g_h[NMAX * DIM];
__device__ float g_qwe[(size_t)NMAX * 64];
__device__ float g_qbe[NMAX * 4];
__device__ float g_eperm[(size_t)EMAX * EDIM];
__device__ int   g_src[EMAX];
__device__ int   g_dst[EMAX];
__device__ int   g_ssrc[EMAX];
__device__ int   g_eid[EMAX];
__device__ int   g_cnt[NMAX];
__device__ int   g_rowptr[NMAX + 1];
__device__ int   g_woff[NMAX];
__device__ int   g_bsum[64];
__device__ int   g_boff[64];
__device__ int   g_idx64;

// ---------------------------------------------------------------------------
// Helpers
// ---------------------------------------------------------------------------
__device__ __forceinline__ float warpSum(float v) {
#pragma unroll
    for (int off = 16; off; off >>= 1)
        v += __shfl_xor_sync(0xffffffffu, v, off);
    return v;
}

__device__ __forceinline__ float to_tf32(float x) {
    float r;
    asm("cvt.rna.tf32.f32 %0, %1;" : "=f"(r) : "f"(x));
    return r;
}

__device__ __forceinline__ void mma_tf32(float c[4],
                                         unsigned a0, unsigned a1, unsigned a2, unsigned a3,
                                         unsigned b0, unsigned b1) {
    asm volatile(
        "mma.sync.aligned.m16n8k8.row.col.f32.tf32.tf32.f32 "
        "{%0,%1,%2,%3},{%4,%5,%6,%7},{%8,%9},{%0,%1,%2,%3};"
        : "+f"(c[0]), "+f"(c[1]), "+f"(c[2]), "+f"(c[3])
        : "r"(a0), "r"(a1), "r"(a2), "r"(a3), "r"(b0), "r"(b1));
}

// ---------------------------------------------------------------------------
// Index detect (parallel) / convert (+fused histogram)
// ---------------------------------------------------------------------------
__global__ void detect_idx_kernel(const int* raw) {
    int t = threadIdx.x;   // 32 threads
    int hi_nz = 0, lo_nz = 0;
    for (int i = t; i < 256; i += 32) {
        if (raw[2 * i + 1] != 0) hi_nz = 1;
        if (raw[2 * i] != 0) lo_nz = 1;
    }
    unsigned hi = __ballot_sync(0xffffffffu, hi_nz);
    unsigned lo = __ballot_sync(0xffffffffu, lo_nz);
    if (t == 0) g_idx64 = (hi == 0u && lo != 0u) ? 1 : 0;
}

__global__ void convert_idx_kernel(const void* raw, int E) {
    int i = blockIdx.x * blockDim.x + threadIdx.x;
    if (i >= E) return;
    int s, d;
    if (g_idx64) {
        const long long* p = (const long long*)raw;
        s = (int)p[i];
        d = (int)p[E + i];
    } else {
        const int* p = (const int*)raw;
        s = p[i];
        d = p[E + i];
    }
    g_src[i] = s;
    g_dst[i] = d;
    atomicAdd(&g_cnt[d], 1);
}

// ---------------------------------------------------------------------------
// 3-phase exclusive scan
// ---------------------------------------------------------------------------
__global__ void __launch_bounds__(1024)
scanA_kernel(int N) {
    __shared__ int wsum[32];
    int t = threadIdx.x;
    int i = blockIdx.x * 1024 + t;
    int v = (i < N) ? g_cnt[i] : 0;
    int inc = v;
#pragma unroll
    for (int off = 1; off < 32; off <<= 1) {
        int u = __shfl_up_sync(0xffffffffu, inc, off);
        if ((t & 31) >= off) inc += u;
    }
    if ((t & 31) == 31) wsum[t >> 5] = inc;
    __syncthreads();
    if (t < 32) {
        int w = wsum[t];
        int wi = w;
#pragma unroll
        for (int off = 1; off < 32; off <<= 1) {
            int u = __shfl_up_sync(0xffffffffu, wi, off);
            if (t >= off) wi += u;
        }
        wsum[t] = wi - w;
    }
    __syncthreads();
    int exc = inc - v + wsum[t >> 5];
    if (i < N) g_rowptr[i] = exc;
    if (t == 1023) g_bsum[blockIdx.x] = exc + v;
}

__global__ void scanB_kernel(int nb, int N, int E) {
    int lane = threadIdx.x;
    int v0 = (lane < nb) ? g_bsum[lane] : 0;
    int v1 = (32 + lane < nb) ? g_bsum[32 + lane] : 0;
    int i0 = v0, i1 = v1;
#pragma unroll
    for (int off = 1; off < 32; off <<= 1) {
        int u = __shfl_up_sync(0xffffffffu, i0, off);
        if (lane >= off) i0 += u;
        int u2 = __shfl_up_sync(0xffffffffu, i1, off);
        if (lane >= off) i1 += u2;
    }
    int tot0 = __shfl_sync(0xffffffffu, i0, 31);
    i1 += tot0;
    g_boff[lane] = i0 - v0;
    g_boff[32 + lane] = i1 - v1;
    if (lane == 0) g_rowptr[N] = E;
}

__global__ void __launch_bounds__(1024)
scanC_kernel(int N) {
    int i = blockIdx.x * 1024 + threadIdx.x;
    if (i < N) {
        int r = g_rowptr[i] + g_boff[blockIdx.x];
        g_rowptr[i] = r;
        g_woff[i] = r;
    }
}

__global__ void scatter_kernel(int E) {
    int i = blockIdx.x * blockDim.x + threadIdx.x;
    if (i >= E) return;
    int d = g_dst[i];
    int pos = atomicAdd(&g_woff[d], 1);
    g_ssrc[pos] = g_src[i];
    g_eid[pos] = i;
}

__global__ void __launch_bounds__(256)
permute_eattr_kernel(const float* __restrict__ eattr, int E) {
    int i = blockIdx.x * blockDim.x + threadIdx.x;
    if (i >= E * 4) return;
    int p = i >> 2, q = (i & 3) * 4;
    int e = g_eid[p];
    *(float4*)&g_eperm[(size_t)p * EDIM + q] =
        *(const float4*)&eattr[(size_t)e * EDIM + q];
}

// ---------------------------------------------------------------------------
// TF32 MMA core: BK=16, double-buffered smem, ONE sync per k-tile.
// ---------------------------------------------------------------------------
__device__ __forceinline__ void mma_core(
    const float* __restrict__ A, const float* __restrict__ B,
    int M, int K, int Nout, int n_base, int m0,
    float (&acc)[2][8][4], float (&As)[2][128][20], float (&Bs)[2][16][136])
{
    const int tid = threadIdx.x;
    const int lane = tid & 31;
    const int wid = tid >> 5;
    const int warp_m = wid & 3;
    const int warp_n = wid >> 2;

#pragma unroll
    for (int i = 0; i < 2; i++)
#pragma unroll
        for (int j = 0; j < 8; j++)
#pragma unroll
            for (int c = 0; c < 4; c++) acc[i][j][c] = 0.f;

    float4 pa[2], pb[2];

#define LOAD_TILE(K0)                                                         \
    {                                                                         \
        const int k0c_ = (K0);                                                \
        _Pragma("unroll")                                                     \
        for (int _t = 0; _t < 2; _t++) {                                      \
            int j = tid + _t * 256;                                           \
            int r = j >> 2, q = (j & 3) * 4;                                  \
            pa[_t] = (m0 + r < M)                                             \
                ? *(const float4*)&A[(size_t)(m0 + r) * K + k0c_ + q]         \
                : make_float4(0.f, 0.f, 0.f, 0.f);                            \
            int br = j >> 5, c4 = (j & 31) * 4;                               \
            pb[_t] = *(const float4*)&B[(size_t)(k0c_ + br) * Nout + n_base + c4]; \
        }                                                                     \
    }

#define STORE_TILE(BUF)                                                       \
    {                                                                         \
        const int buf_ = (BUF);                                               \
        _Pragma("unroll")                                                     \
        for (int _t = 0; _t < 2; _t++) {                                      \
            int j = tid + _t * 256;                                           \
            int r = j >> 2, q = (j & 3) * 4;                                  \
            As[buf_][r][q + 0] = to_tf32(pa[_t].x);                           \
            As[buf_][r][q + 1] = to_tf32(pa[_t].y);                           \
            As[buf_][r][q + 2] = to_tf32(pa[_t].z);                           \
            As[buf_][r][q + 3] = to_tf32(pa[_t].w);                           \
            int br = j >> 5, c4 = (j & 31) * 4;                               \
            Bs[buf_][br][c4 + 0] = to_tf32(pb[_t].x);                         \
            Bs[buf_][br][c4 + 1] = to_tf32(pb[_t].y);                         \
            Bs[buf_][br][c4 + 2] = to_tf32(pb[_t].z);                         \
            Bs[buf_][br][c4 + 3] = to_tf32(pb[_t].w);                         \
        }                                                                     \
    }

    LOAD_TILE(0);
    STORE_TILE(0);
    __syncthreads();

    const int T = K >> 4;
#pragma unroll 2
    for (int t = 0; t < T; t++) {
        if (t + 1 < T) LOAD_TILE((t + 1) << 4);
        const int b = t & 1;
#pragma unroll
        for (int kk = 0; kk < 16; kk += 8) {
            unsigned bf[8][2];
#pragma unroll
            for (int nt = 0; nt < 8; nt++) {
                int n = warp_n * 64 + nt * 8 + (lane >> 2);
                bf[nt][0] = __float_as_uint(Bs[b][kk + (lane & 3)][n]);
                bf[nt][1] = __float_as_uint(Bs[b][kk + 4 + (lane & 3)][n]);
            }
#pragma unroll
            for (int mt = 0; mt < 2; mt++) {
                int r0 = warp_m * 32 + mt * 16 + (lane >> 2);
                unsigned a0 = __float_as_uint(As[b][r0][kk + (lane & 3)]);
                unsigned a1 = __float_as_uint(As[b][r0 + 8][kk + (lane & 3)]);
                unsigned a2 = __float_as_uint(As[b][r0][kk + 4 + (lane & 3)]);
                unsigned a3 = __float_as_uint(As[b][r0 + 8][kk + 4 + (lane & 3)]);
#pragma unroll
                for (int nt = 0; nt < 8; nt++)
                    mma_tf32(acc[mt][nt], a0, a1, a2, a3, bf[nt][0], bf[nt][1]);
            }
        }
        if (t + 1 < T) STORE_TILE((t + 1) & 1);
        __syncthreads();
    }
#undef LOAD_TILE
#undef STORE_TILE
}

// ---------------------------------------------------------------------------
// proj4 (q/k/v/skip) via tensor cores; q scaled at store.
// ---------------------------------------------------------------------------
__global__ void __launch_bounds__(256)
proj_mma_kernel(const float* __restrict__ A,
                const float* __restrict__ Wq, const float* __restrict__ bq,
                const float* __restrict__ Wk, const float* __restrict__ bk,
                const float* __restrict__ Wv, const float* __restrict__ bv,
                const float* __restrict__ Ws, const float* __restrict__ bs,
                int M)
{
    const float* B; const float* bias; float* C; float scale;
    switch (blockIdx.y) {
        case 0: B = Wq; bias = bq; C = g_q;  scale = QSCALE; break;
        case 1: B = Wk; bias = bk; C = g_k;  scale = 1.f;    break;
        case 2: B = Wv; bias = bv; C = g_v;  scale = 1.f;    break;
        default: B = Ws; bias = bs; C = g_xr; scale = 1.f;   break;
    }
    __shared__ float As[2][128][20];
    __shared__ float Bs[2][16][136];
    float acc[2][8][4];
    const int m0 = blockIdx.x * 128;
    mma_core(A, B, M, DIM, DIM, 0, m0, acc, As, Bs);

    const int lane = threadIdx.x & 31;
    const int wid = threadIdx.x >> 5;
    const int warp_m = wid & 3, warp_n = wid >> 2;
#pragma unroll
    for (int mt = 0; mt < 2; mt++)
#pragma unroll
        for (int h2 = 0; h2 < 2; h2++) {
            int m = m0 + warp_m * 32 + mt * 16 + (lane >> 2) + h2 * 8;
            if (m >= M) continue;
#pragma unroll
            for (int nt = 0; nt < 8; nt++) {
                int col = warp_n * 64 + nt * 8 + (lane & 3) * 2;
                float2 st;
                st.x = (acc[mt][nt][h2 * 2]     + __ldg(&bias[col]))     * scale;
                st.y = (acc[mt][nt][h2 * 2 + 1] + __ldg(&bias[col + 1])) * scale;
                *(float2*)&C[(size_t)m * DIM + col] = st;
            }
        }
}

// ---------------------------------------------------------------------------
// Fused FFN: out = LN( h + relu(h@Wf1+bf1)@Wf2 + bf2 ; g2,b2 )
// ---------------------------------------------------------------------------
#define FFN_SMEM_FLOATS (2 * 128 * 132 + 2 * 16 * 136)

__global__ void __launch_bounds__(256)
ffn_fused_kernel(const float* __restrict__ A, const float* __restrict__ Wf1,
                 const float* __restrict__ bf1, const float* __restrict__ Wf2,
                 const float* __restrict__ bf2, float* __restrict__ C,
                 const float* __restrict__ gamma, const float* __restrict__ betap,
                 int M)
{
    extern __shared__ float sm[];
    float (*H)[132] = (float(*)[132])sm;
    float (*T)[132] = (float(*)[132])(sm + 128 * 132);
    float (*Bs)[16][136] = (float(*)[16][136])(sm + 2 * 128 * 132);

    const int tid = threadIdx.x;
    const int lane = tid & 31;
    const int wid = tid >> 5;
    const int warp_m = wid & 3;
    const int warp_n = wid >> 2;
    const int m0 = blockIdx.x * 128;

#pragma unroll
    for (int t = 0; t < 16; t++) {
        int j = tid + t * 256;
        int r = j >> 5, c4 = (j & 31) * 4;
        float4 v = (m0 + r < M) ? *(const float4*)&A[(size_t)(m0 + r) * DIM + c4]
                                : make_float4(0.f, 0.f, 0.f, 0.f);
        H[r][c4 + 0] = to_tf32(v.x);
        H[r][c4 + 1] = to_tf32(v.y);
        H[r][c4 + 2] = to_tf32(v.z);
        H[r][c4 + 3] = to_tf32(v.w);
    }
    __syncthreads();

    float acc2[2][8][4];
#pragma unroll
    for (int i = 0; i < 2; i++)
#pragma unroll
        for (int j = 0; j < 8; j++)
#pragma unroll
            for (int c = 0; c < 4; c++) acc2[i][j][c] = 0.f;

    float4 pbv[2];

#define LOADB1(CH_, T0)                                                       \
    {                                                                         \
        _Pragma("unroll")                                                     \
        for (int _t = 0; _t < 2; _t++) {                                      \
            int j = tid + _t * 256;                                           \
            int br = j >> 5, c4 = (j & 31) * 4;                               \
            pbv[_t] = *(const float4*)&Wf1[(size_t)((T0) * 16 + br) * 512     \
                                           + (CH_) * 128 + c4];               \
        }                                                                     \
    }
#define LOADB2(CH_, T0)                                                       \
    {                                                                         \
        _Pragma("unroll")                                                     \
        for (int _t = 0; _t < 2; _t++) {                                      \
            int j = tid + _t * 256;                                           \
            int br = j >> 5, c4 = (j & 31) * 4;                               \
            pbv[_t] = *(const float4*)&Wf2[(size_t)((CH_) * 128 + (T0) * 16 + br) * 128 + c4]; \
        }                                                                     \
    }
#define STOREB(BUF)                                                           \
    {                                                                         \
        const int buf_ = (BUF);                                               \
        _Pragma("unroll")                                                     \
        for (int _t = 0; _t < 2; _t++) {                                      \
            int j = tid + _t * 256;                                           \
            int br = j >> 5, c4 = (j & 31) * 4;                               \
            Bs[buf_][br][c4 + 0] = to_tf32(pbv[_t].x);                        \
            Bs[buf_][br][c4 + 1] = to_tf32(pbv[_t].y);                        \
            Bs[buf_][br][c4 + 2] = to_tf32(pbv[_t].z);                        \
            Bs[buf_][br][c4 + 3] = to_tf32(pbv[_t].w);                        \
        }                                                                     \
    }

#define GEMM_STEP(ACC, ASRC, B_, KGLOB)                                       \
    {                                                                         \
        _Pragma("unroll")                                                     \
        for (int kk0 = 0; kk0 < 16; kk0 += 8) {                               \
            int kk = (KGLOB) + kk0;                                           \
            unsigned bf[8][2];                                                \
            _Pragma("unroll")                                                 \
            for (int nt = 0; nt < 8; nt++) {                                  \
                int n = warp_n * 64 + nt * 8 + (lane >> 2);                   \
                bf[nt][0] = __float_as_uint(Bs[B_][kk0 + (lane & 3)][n]);     \
                bf[nt][1] = __float_as_uint(Bs[B_][kk0 + 4 + (lane & 3)][n]); \
            }                                                                 \
            _Pragma("unroll")                                                 \
            for (int mt = 0; mt < 2; mt++) {                                  \
                int r0 = warp_m * 32 + mt * 16 + (lane >> 2);                 \
                unsigned a0 = __float_as_uint(ASRC[r0][kk + (lane & 3)]);     \
                unsigned a1 = __float_as_uint(ASRC[r0 + 8][kk + (lane & 3)]); \
                unsigned a2 = __float_as_uint(ASRC[r0][kk + 4 + (lane & 3)]); \
                unsigned a3 = __float_as_uint(ASRC[r0 + 8][kk + 4 + (lane & 3)]); \
                _Pragma("unroll")                                             \
                for (int nt = 0; nt < 8; nt++)                                \
                    mma_tf32(ACC[mt][nt], a0, a1, a2, a3, bf[nt][0], bf[nt][1]); \
            }                                                                 \
        }                                                                     \
    }

#pragma unroll 1
    for (int c = 0; c < 4; c++) {
        float acc1[2][8][4];
#pragma unroll
        for (int i = 0; i < 2; i++)
#pragma unroll
            for (int j = 0; j < 8; j++)
#pragma unroll
                for (int cc = 0; cc < 4; cc++) acc1[i][j][cc] = 0.f;

        LOADB1(c, 0);
        STOREB(0);
        __syncthreads();
#pragma unroll
        for (int t = 0; t < 8; t++) {
            if (t < 7) LOADB1(c, t + 1);
            GEMM_STEP(acc1, H, t & 1, t * 16);
            if (t < 7) STOREB((t + 1) & 1);
            __syncthreads();
        }

#pragma unroll
        for (int mt = 0; mt < 2; mt++)
#pragma unroll
            for (int h2 = 0; h2 < 2; h2++) {
                int row = warp_m * 32 + mt * 16 + (lane >> 2) + h2 * 8;
#pragma unroll
                for (int nt = 0; nt < 8; nt++) {
                    int col = warp_n * 64 + nt * 8 + (lane & 3) * 2;
                    int gcol = c * 128 + col;
                    float t0 = fmaxf(acc1[mt][nt][h2 * 2]     + __ldg(&bf1[gcol]), 0.f);
                    float t1 = fmaxf(acc1[mt][nt][h2 * 2 + 1] + __ldg(&bf1[gcol + 1]), 0.f);
                    T[row][col]     = to_tf32(t0);
                    T[row][col + 1] = to_tf32(t1);
                }
            }

        LOADB2(c, 0);
        STOREB(0);
        __syncthreads();
#pragma unroll
        for (int t = 0; t < 8; t++) {
            if (t < 7) LOADB2(c, t + 1);
            GEMM_STEP(acc2, T, t & 1, t * 16);
            if (t < 7) STOREB((t + 1) & 1);
            __syncthreads();
        }
    }
#undef LOADB1
#undef LOADB2
#undef STOREB
#undef GEMM_STEP

    float (*pr)[2] = (float(*)[2])H;
    float mu[2][2];
#pragma unroll
    for (int mt = 0; mt < 2; mt++)
#pragma unroll
        for (int h2 = 0; h2 < 2; h2++) {
            int row = warp_m * 32 + mt * 16 + (lane >> 2) + h2 * 8;
            int m = m0 + row;
            float s = 0.f;
#pragma unroll
            for (int nt = 0; nt < 8; nt++) {
                int col = warp_n * 64 + nt * 8 + (lane & 3) * 2;
                float r0 = (m < M) ? __ldg(&A[(size_t)m * DIM + col])     : 0.f;
                float r1 = (m < M) ? __ldg(&A[(size_t)m * DIM + col + 1]) : 0.f;
                float t0 = acc2[mt][nt][h2 * 2]     + __ldg(&bf2[col])     + r0;
                float t1 = acc2[mt][nt][h2 * 2 + 1] + __ldg(&bf2[col + 1]) + r1;
                acc2[mt][nt][h2 * 2] = t0;
                acc2[mt][nt][h2 * 2 + 1] = t1;
                s += t0 + t1;
            }
            s += __shfl_xor_sync(0xffffffffu, s, 1);
            s += __shfl_xor_sync(0xffffffffu, s, 2);
            if ((lane & 3) == 0) pr[row][warp_n] = s;
        }
    __syncthreads();
#pragma unroll
    for (int mt = 0; mt < 2; mt++)
#pragma unroll
        for (int h2 = 0; h2 < 2; h2++) {
            int row = warp_m * 32 + mt * 16 + (lane >> 2) + h2 * 8;
            mu[mt][h2] = (pr[row][0] + pr[row][1]) * (1.0f / 128.0f);
        }
    __syncthreads();
#pragma unroll
    for (int mt = 0; mt < 2; mt++)
#pragma unroll
        for (int h2 = 0; h2 < 2; h2++) {
            int row = warp_m * 32 + mt * 16 + (lane >> 2) + h2 * 8;
            float vs = 0.f;
#pragma unroll
            for (int nt = 0; nt < 8; nt++) {
                float d0 = acc2[mt][nt][h2 * 2]     - mu[mt][h2];
                float d1 = acc2[mt][nt][h2 * 2 + 1] - mu[mt][h2];
                vs += d0 * d0 + d1 * d1;
            }
            vs += __shfl_xor_sync(0xffffffffu, vs, 1);
            vs += __shfl_xor_sync(0xffffffffu, vs, 2);
            if ((lane & 3) == 0) pr[row][warp_n] = vs;
        }
    __syncthreads();
#pragma unroll
    for (int mt = 0; mt < 2; mt++)
#pragma unroll
        for (int h2 = 0; h2 < 2; h2++) {
            int row = warp_m * 32 + mt * 16 + (lane >> 2) + h2 * 8;
            int m = m0 + row;
            if (m >= M) continue;
            float var = (pr[row][0] + pr[row][1]) * (1.0f / 128.0f);
            float inv = rsqrtf(var + 1e-5f);
#pragma unroll
            for (int nt = 0; nt < 8; nt++) {
                int col = warp_n * 64 + nt * 8 + (lane & 3) * 2;
                float2 st;
                st.x = (acc2[mt][nt][h2 * 2]     - mu[mt][h2]) * inv * __ldg(&gamma[col])     + __ldg(&betap[col]);
                st.y = (acc2[mt][nt][h2 * 2 + 1] - mu[mt][h2]) * inv * __ldg(&gamma[col + 1]) + __ldg(&betap[col + 1]);
                *(float2*)&C[(size_t)m * DIM + col] = st;
            }
        }
}

// ---------------------------------------------------------------------------
// qwe precompute
// ---------------------------------------------------------------------------
__global__ void __launch_bounds__(256)
qwe_kernel(const float* __restrict__ We, const float* __restrict__ be, int N)
{
    __shared__ float sWe[EDIM * DIM];
    __shared__ float sq[4][DIM];
    __shared__ float sbe[DIM];
    int tid = threadIdx.x;
    for (int i = tid; i < EDIM * DIM; i += 256) sWe[i] = We[i];
    if (tid < DIM) sbe[tid] = be[tid];
    int n0 = blockIdx.x * 4;
    for (int i = tid; i < 4 * DIM; i += 256) {
        int nn = i >> 7, c = i & 127;
        sq[nn][c] = (n0 + nn < N) ? g_q[(size_t)(n0 + nn) * DIM + c] : 0.f;
    }
    __syncthreads();
    int nn = tid >> 6, r = tid & 63, h = r >> 4, i = r & 15;
    int n = n0 + nn;
    if (n >= N) return;
    float a = 0.f;
#pragma unroll
    for (int c = 0; c < 32; c++)
        a = fmaf(sq[nn][h * 32 + c], sWe[i * DIM + h * 32 + c], a);
    g_qwe[(size_t)n * 64 + h * 16 + i] = a;
    if (i == 0) {
        float qb = 0.f;
#pragma unroll
        for (int c = 0; c < 32; c++)
            qb = fmaf(sq[nn][h * 32 + c], sbe[h * 32 + c], qb);
        g_qbe[n * 4 + h] = qb;
    }
}

// ---------------------------------------------------------------------------
// Warp-per-node attention with 4-edge software pipeline + beta gate + LN1.
// ---------------------------------------------------------------------------
__global__ void __launch_bounds__(256)
node_attn_kernel(const float* __restrict__ We, const float* __restrict__ be,
                 const float* __restrict__ x,  const float* __restrict__ Wbeta,
                 const float* __restrict__ g1, const float* __restrict__ b1,
                 int N)
{
    __shared__ float sWe[EDIM][DIM];
    __shared__ float sbe[DIM];
    for (int i = threadIdx.x; i < EDIM * DIM; i += 256)
        ((float*)sWe)[i] = We[i];
    if (threadIdx.x < DIM) sbe[threadIdx.x] = be[threadIdx.x];
    __syncthreads();

    const int lane = threadIdx.x & 31;
    const int g = lane >> 3;
    const int l8 = lane & 7;
    const int ch0 = g * 32 + l8 * 4;
    const int warp = blockIdx.x * (blockDim.x >> 5) + (threadIdx.x >> 5);
    const int nwarps = gridDim.x * (blockDim.x >> 5);

    for (int n = warp; n < N; n += nwarps) {
        float4 q4 = *(const float4*)&g_q[(size_t)n * DIM + ch0];
        float2 qwe2 = *(const float2*)&g_qwe[(size_t)n * 64 + g * 16 + 2 * l8];
        float qbe = g_qbe[n * 4 + g];

        float4 acc = make_float4(0.f, 0.f, 0.f, 0.f);
        float s0 = 0.f, s1 = 0.f, den = 0.f;

        int beg = g_rowptr[n], end = g_rowptr[n + 1];
        int p = beg;
        for (; p + 4 <= end; p += 4) {
            int sA = __ldg(&g_ssrc[p]);
            int sB = __ldg(&g_ssrc[p + 1]);
            int sC = __ldg(&g_ssrc[p + 2]);
            int sD = __ldg(&g_ssrc[p + 3]);
            float4 kA = *(const float4*)&g_k[(size_t)sA * DIM + ch0];
            float4 kB = *(const float4*)&g_k[(size_t)sB * DIM + ch0];
            float4 kC = *(const float4*)&g_k[(size_t)sC * DIM + ch0];
            float4 kD = *(const float4*)&g_k[(size_t)sD * DIM + ch0];
            float4 vA = *(const float4*)&g_v[(size_t)sA * DIM + ch0];
            float4 vB = *(const float4*)&g_v[(size_t)sB * DIM + ch0];
            float4 vC = *(const float4*)&g_v[(size_t)sC * DIM + ch0];
            float4 vD = *(const float4*)&g_v[(size_t)sD * DIM + ch0];
            float2 aA = *(const float2*)&g_eperm[(size_t)p * EDIM + 2 * l8];
            float2 aB = *(const float2*)&g_eperm[(size_t)(p + 1) * EDIM + 2 * l8];
            float2 aC = *(const float2*)&g_eperm[(size_t)(p + 2) * EDIM + 2 * l8];
            float2 aD = *(const float2*)&g_eperm[(size_t)(p + 3) * EDIM + 2 * l8];

            float pA = q4.x * kA.x + q4.y * kA.y + q4.z * kA.z + q4.w * kA.w
                     + aA.x * qwe2.x + aA.y * qwe2.y;
            float pB = q4.x * kB.x + q4.y * kB.y + q4.z * kB.z + q4.w * kB.w
                     + aB.x * qwe2.x + aB.y * qwe2.y;
            float pC = q4.x * kC.x + q4.y * kC.y + q4.z * kC.z + q4.w * kC.w
                     + aC.x * qwe2.x + aC.y * qwe2.y;
            float pD = q4.x * kD.x + q4.y * kD.y + q4.z * kD.z + q4.w * kD.w
                     + aD.x * qwe2.x + aD.y * qwe2.y;
            pA += __shfl_xor_sync(0xffffffffu, pA, 1);
            pB += __shfl_xor_sync(0xffffffffu, pB, 1);
            pC += __shfl_xor_sync(0xffffffffu, pC, 1);
            pD += __shfl_xor_sync(0xffffffffu, pD, 1);
            pA += __shfl_xor_sync(0xffffffffu, pA, 2);
            pB += __shfl_xor_sync(0xffffffffu, pB, 2);
            pC += __shfl_xor_sync(0xffffffffu, pC, 2);
            pD += __shfl_xor_sync(0xffffffffu, pD, 2);
            pA += __shfl_xor_sync(0xffffffffu, pA, 4);
            pB += __shfl_xor_sync(0xffffffffu, pB, 4);
            pC += __shfl_xor_sync(0xffffffffu, pC, 4);
            pD += __shfl_xor_sync(0xffffffffu, pD, 4);
            float eA = __expf(pA + qbe);
            float eB = __expf(pB + qbe);
            float eC = __expf(pC + qbe);
            float eD = __expf(pD + qbe);
            den += eA;
            acc.x = fmaf(eA, vA.x, acc.x); acc.y = fmaf(eA, vA.y, acc.y);
            acc.z = fmaf(eA, vA.z, acc.z); acc.w = fmaf(eA, vA.w, acc.w);
            s0 = fmaf(eA, aA.x, s0); s1 = fmaf(eA, aA.y, s1);
            den += eB;
            acc.x = fmaf(eB, vB.x, acc.x); acc.y = fmaf(eB, vB.y, acc.y);
            acc.z = fmaf(eB, vB.z, acc.z); acc.w = fmaf(eB, vB.w, acc.w);
            s0 = fmaf(eB, aB.x, s0); s1 = fmaf(eB, aB.y, s1);
            den += eC;
            acc.x = fmaf(eC, vC.x, acc.x); acc.y = fmaf(eC, vC.y, acc.y);
            acc.z = fmaf(eC, vC.z, acc.z); acc.w = fmaf(eC, vC.w, acc.w);
            s0 = fmaf(eC, aC.x, s0); s1 = fmaf(eC, aC.y, s1);
            den += eD;
            acc.x = fmaf(eD, vD.x, acc.x); acc.y = fmaf(eD, vD.y, acc.y);
            acc.z = fmaf(eD, vD.z, acc.z); acc.w = fmaf(eD, vD.w, acc.w);
            s0 = fmaf(eD, aD.x, s0); s1 = fmaf(eD, aD.y, s1);
        }
        for (; p < end; p++) {
            int sA = __ldg(&g_ssrc[p]);
            float2 aA = *(const float2*)&g_eperm[(size_t)p * EDIM + 2 * l8];
            float4 kA = *(const float4*)&g_k[(size_t)sA * DIM + ch0];
            float4 vA = *(const float4*)&g_v[(size_t)sA * DIM + ch0];
            float pp = q4.x * kA.x + q4.y * kA.y + q4.z * kA.z + q4.w * kA.w
                     + aA.x * qwe2.x + aA.y * qwe2.y;
            pp += __shfl_xor_sync(0xffffffffu, pp, 1);
            pp += __shfl_xor_sync(0xffffffffu, pp, 2);
            pp += __shfl_xor_sync(0xffffffffu, pp, 4);
            float ea = __expf(pp + qbe);
            den += ea;
            acc.x = fmaf(ea, vA.x, acc.x); acc.y = fmaf(ea, vA.y, acc.y);
            acc.z = fmaf(ea, vA.z, acc.z); acc.w = fmaf(ea, vA.w, acc.w);
            s0 = fmaf(ea, aA.x, s0); s1 = fmaf(ea, aA.y, s1);
        }

        float4 ev;
        ev.x = den * sbe[ch0];
        ev.y = den * sbe[ch0 + 1];
        ev.z = den * sbe[ch0 + 2];
        ev.w = den * sbe[ch0 + 3];
#pragma unroll
        for (int jj = 0; jj < 8; jj++) {
            int srcl = (g << 3) | jj;
            float sj0 = __shfl_sync(0xffffffffu, s0, srcl);
            float sj1 = __shfl_sync(0xffffffffu, s1, srcl);
            float4 w0 = *(const float4*)&sWe[2 * jj][ch0];
            float4 w1 = *(const float4*)&sWe[2 * jj + 1][ch0];
            ev.x += sj0 * w0.x + sj1 * w1.x;
            ev.y += sj0 * w0.y + sj1 * w1.y;
            ev.z += sj0 * w0.z + sj1 * w1.z;
            ev.w += sj0 * w0.w + sj1 * w1.w;
        }
        float rden = 1.0f / (den + 1e-16f);
        float o[4] = {(acc.x + ev.x) * rden, (acc.y + ev.y) * rden,
                      (acc.z + ev.z) * rden, (acc.w + ev.w) * rden};

        float4 xr4 = *(const float4*)&g_xr[(size_t)n * DIM + ch0];
        float4 wb0 = *(const float4*)&Wbeta[ch0];
        float4 wb1 = *(const float4*)&Wbeta[DIM + ch0];
        float4 wb2 = *(const float4*)&Wbeta[2 * DIM + ch0];
        float xr[4] = {xr4.x, xr4.y, xr4.z, xr4.w};
        float z = wb0.x * o[0] + wb1.x * xr[0] + wb2.x * (o[0] - xr[0])
                + wb0.y * o[1] + wb1.y * xr[1] + wb2.y * (o[1] - xr[1])
                + wb0.z * o[2] + wb1.z * xr[2] + wb2.z * (o[2] - xr[2])
                + wb0.w * o[3] + wb1.w * xr[3] + wb2.w * (o[3] - xr[3]);
        z = warpSum(z);
        float beta = 1.0f / (1.0f + __expf(-z));

        float4 xv = *(const float4*)&x[(size_t)n * DIM + ch0];
        float xx[4] = {xv.x, xv.y, xv.z, xv.w};
        float tv[4], ts = 0.f;
#pragma unroll
        for (int c = 0; c < 4; c++) {
            tv[c] = xx[c] + beta * xr[c] + (1.0f - beta) * o[c];
            ts += tv[c];
        }
        float mu = warpSum(ts) * (1.0f / 128.0f);
        float vs = 0.f;
#pragma unroll
        for (int c = 0; c < 4; c++) { tv[c] -= mu; vs += tv[c] * tv[c]; }
        float var = warpSum(vs) * (1.0f / 128.0f);
        float inv = rsqrtf(var + 1e-5f);

        float4 gg = *(const float4*)&g1[ch0];
        float4 bb = *(const float4*)&b1[ch0];
        float4 st;
        st.x = tv[0] * inv * gg.x + bb.x;
        st.y = tv[1] * inv * gg.y + bb.y;
        st.z = tv[2] * inv * gg.z + bb.z;
        st.w = tv[3] * inv * gg.w + bb.w;
        *(float4*)&g_h[(size_t)n * DIM + ch0] = st;
    }
}

// ---------------------------------------------------------------------------
// Launch (fork-join streams: CSR chain || projections; fused FFN)
// ---------------------------------------------------------------------------
extern "C" void kernel_launch(void* const* d_in, const int* in_sizes, int n_in,
                              void* d_out, int out_size)
{
    const float* x      = (const float*)d_in[0];
    const void*  eidx   = d_in[1];
    const float* eattr  = (const float*)d_in[2];
    const float* Wq     = (const float*)d_in[3];
    const float* bq     = (const float*)d_in[4];
    const float* Wk     = (const float*)d_in[5];
    const float* bk     = (const float*)d_in[6];
    const float* Wv     = (const float*)d_in[7];
    const float* bv     = (const float*)d_in[8];
    const float* We     = (const float*)d_in[9];
    const float* be     = (const float*)d_in[10];
    const float* Ws     = (const float*)d_in[11];
    const float* bs     = (const float*)d_in[12];
    const float* Wbeta  = (const float*)d_in[13];
    const float* g1     = (const float*)d_in[14];
    const float* b1     = (const float*)d_in[15];
    const float* Wf1    = (const float*)d_in[16];
    const float* bf1    = (const float*)d_in[17];
    const float* Wf2    = (const float*)d_in[18];
    const float* bf2    = (const float*)d_in[19];
    const float* g2     = (const float*)d_in[20];
    const float* b2     = (const float*)d_in[21];

    const int N = in_sizes[0] / DIM;
    const int E = in_sizes[1] / 2;

    float *h, *cnt;
    cudaGetSymbolAddress((void**)&h, g_h);
    cudaGetSymbolAddress((void**)&cnt, g_cnt);

    static cudaStream_t s1 = nullptr;
    static cudaEvent_t evFork = nullptr, evCsr = nullptr;
    if (!s1) {
        cudaStreamCreate(&s1);
        cudaEventCreateWithFlags(&evFork, cudaEventDisableTiming);
        cudaEventCreateWithFlags(&evCsr, cudaEventDisableTiming);
        cudaFuncSetAttribute(ffn_fused_kernel,
                             cudaFuncAttributeMaxDynamicSharedMemorySize,
                             FFN_SMEM_FLOATS * 4);
    }

    const int nb = (N + 1023) / 1024;
    const int gm = (N + 127) / 128;

    // fork
    cudaEventRecord(evFork, 0);
    cudaStreamWaitEvent(s1, evFork, 0);

    // CSR chain on s1 (cnt zeroed via memset — one less kernel)
    cudaMemsetAsync(cnt, 0, (size_t)N * sizeof(int), s1);
    detect_idx_kernel<<<1, 32, 0, s1>>>((const int*)eidx);
    convert_idx_kernel<<<(E + 255) / 256, 256, 0, s1>>>(eidx, E);
    scanA_kernel<<<nb, 1024, 0, s1>>>(N);
    scanB_kernel<<<1, 32, 0, s1>>>(nb, N, E);
    scanC_kernel<<<nb, 1024, 0, s1>>>(N);
    scatter_kernel<<<(E + 255) / 256, 256, 0, s1>>>(E);
    permute_eattr_kernel<<<(E * 4 + 255) / 256, 256, 0, s1>>>(eattr, E);
    cudaEventRecord(evCsr, s1);

    // projections + qwe on default stream
    dim3 gproj(gm, 4);
    proj_mma_kernel<<<gproj, 256>>>(x, Wq, bq, Wk, bk, Wv, bv, Ws, bs, N);
    qwe_kernel<<<(N + 3) / 4, 256>>>(We, be, N);

    // join
    cudaStreamWaitEvent(0, evCsr, 0);

    node_attn_kernel<<<1184, 256>>>(We, be, x, Wbeta, g1, b1, N);

    // fused FFN + residual + LN2
    ffn_fused_kernel<<<gm, 256, FFN_SMEM_FLOATS * 4>>>(
        h, Wf1, bf1, Wf2, bf2, (float*)d_out, g2, b2, N);
}

// round 12
// speedup vs baseline: 1.0800x; 1.0175x over previous
#include <cuda_runtime.h>
#include <cuda_bf16.h>
#include <math.h>

#define NMAX 50000
#define EMAX 800000
#define DIM  128
#define HEADS 4
#define CH   32
#define EDIM 16
#define QSCALE 0.17677669529663687f   // 1/sqrt(32)

// ---------------------------------------------------------------------------
// Scratch
// ---------------------------------------------------------------------------
__device__ float g_q[NMAX * DIM];
__device__ float g_k[NMAX * DIM];
__device__ float g_v[NMAX * DIM];
__device__ float g_xr[NMAX * DIM];
__device__ float g_h[NMAX * DIM];
__device__ float g_qwe[(size_t)NMAX * 64];
__device__ float g_qbe[NMAX * 4];
__device__ float g_eperm[(size_t)EMAX * EDIM];
__device__ int   g_src[EMAX];
__device__ int   g_dst[EMAX];
__device__ int   g_ssrc[EMAX];
__device__ int   g_eid[EMAX];
__device__ int   g_cnt[NMAX];
__device__ int   g_rowptr[NMAX + 1];
__device__ int   g_woff[NMAX];
__device__ int   g_bsum[64];
__device__ int   g_boff[64];
__device__ int   g_idx64;
__device__ int   g_work;

// ---------------------------------------------------------------------------
// Helpers
// ---------------------------------------------------------------------------
__device__ __forceinline__ float warpSum(float v) {
#pragma unroll
    for (int off = 16; off; off >>= 1)
        v += __shfl_xor_sync(0xffffffffu, v, off);
    return v;
}

__device__ __forceinline__ float to_tf32(float x) {
    float r;
    asm("cvt.rna.tf32.f32 %0, %1;" : "=f"(r) : "f"(x));
    return r;
}

__device__ __forceinline__ void mma_tf32(float c[4],
                                         unsigned a0, unsigned a1, unsigned a2, unsigned a3,
                                         unsigned b0, unsigned b1) {
    asm volatile(
        "mma.sync.aligned.m16n8k8.row.col.f32.tf32.tf32.f32 "
        "{%0,%1,%2,%3},{%4,%5,%6,%7},{%8,%9},{%0,%1,%2,%3};"
        : "+f"(c[0]), "+f"(c[1]), "+f"(c[2]), "+f"(c[3])
        : "r"(a0), "r"(a1), "r"(a2), "r"(a3), "r"(b0), "r"(b1));
}

// ---------------------------------------------------------------------------
// Index detect (parallel) / convert (+fused histogram)
// ---------------------------------------------------------------------------
__global__ void detect_idx_kernel(const int* raw) {
    int t = threadIdx.x;
    int hi_nz = 0, lo_nz = 0;
    for (int i = t; i < 256; i += 32) {
        if (raw[2 * i + 1] != 0) hi_nz = 1;
        if (raw[2 * i] != 0) lo_nz = 1;
    }
    unsigned hi = __ballot_sync(0xffffffffu, hi_nz);
    unsigned lo = __ballot_sync(0xffffffffu, lo_nz);
    if (t == 0) g_idx64 = (hi == 0u && lo != 0u) ? 1 : 0;
}

__global__ void convert_idx_kernel(const void* raw, int E) {
    int i = blockIdx.x * blockDim.x + threadIdx.x;
    if (i >= E) return;
    int s, d;
    if (g_idx64) {
        const long long* p = (const long long*)raw;
        s = (int)p[i];
        d = (int)p[E + i];
    } else {
        const int* p = (const int*)raw;
        s = p[i];
        d = p[E + i];
    }
    g_src[i] = s;
    g_dst[i] = d;
    atomicAdd(&g_cnt[d], 1);
}

// ---------------------------------------------------------------------------
// 3-phase exclusive scan
// ---------------------------------------------------------------------------
__global__ void __launch_bounds__(1024)
scanA_kernel(int N) {
    __shared__ int wsum[32];
    int t = threadIdx.x;
    int i = blockIdx.x * 1024 + t;
    int v = (i < N) ? g_cnt[i] : 0;
    int inc = v;
#pragma unroll
    for (int off = 1; off < 32; off <<= 1) {
        int u = __shfl_up_sync(0xffffffffu, inc, off);
        if ((t & 31) >= off) inc += u;
    }
    if ((t & 31) == 31) wsum[t >> 5] = inc;
    __syncthreads();
    if (t < 32) {
        int w = wsum[t];
        int wi = w;
#pragma unroll
        for (int off = 1; off < 32; off <<= 1) {
            int u = __shfl_up_sync(0xffffffffu, wi, off);
            if (t >= off) wi += u;
        }
        wsum[t] = wi - w;
    }
    __syncthreads();
    int exc = inc - v + wsum[t >> 5];
    if (i < N) g_rowptr[i] = exc;
    if (t == 1023) g_bsum[blockIdx.x] = exc + v;
}

__global__ void scanB_kernel(int nb, int N, int E) {
    int lane = threadIdx.x;
    int v0 = (lane < nb) ? g_bsum[lane] : 0;
    int v1 = (32 + lane < nb) ? g_bsum[32 + lane] : 0;
    int i0 = v0, i1 = v1;
#pragma unroll
    for (int off = 1; off < 32; off <<= 1) {
        int u = __shfl_up_sync(0xffffffffu, i0, off);
        if (lane >= off) i0 += u;
        int u2 = __shfl_up_sync(0xffffffffu, i1, off);
        if (lane >= off) i1 += u2;
    }
    int tot0 = __shfl_sync(0xffffffffu, i0, 31);
    i1 += tot0;
    g_boff[lane] = i0 - v0;
    g_boff[32 + lane] = i1 - v1;
    if (lane == 0) g_rowptr[N] = E;
}

__global__ void __launch_bounds__(1024)
scanC_kernel(int N) {
    int i = blockIdx.x * 1024 + threadIdx.x;
    if (i < N) {
        int r = g_rowptr[i] + g_boff[blockIdx.x];
        g_rowptr[i] = r;
        g_woff[i] = r;
    }
}

__global__ void scatter_kernel(int E) {
    int i = blockIdx.x * blockDim.x + threadIdx.x;
    if (i >= E) return;
    int d = g_dst[i];
    int pos = atomicAdd(&g_woff[d], 1);
    g_ssrc[pos] = g_src[i];
    g_eid[pos] = i;
}

__global__ void __launch_bounds__(256)
permute_eattr_kernel(const float* __restrict__ eattr, int E) {
    int i = blockIdx.x * blockDim.x + threadIdx.x;
    if (i >= E * 4) return;
    int p = i >> 2, q = (i & 3) * 4;
    int e = g_eid[p];
    *(float4*)&g_eperm[(size_t)p * EDIM + q] =
        *(const float4*)&eattr[(size_t)e * EDIM + q];
}

// ---------------------------------------------------------------------------
// TF32 MMA core: BK=16, double-buffered smem, ONE sync per k-tile.
// ---------------------------------------------------------------------------
__device__ __forceinline__ void mma_core(
    const float* __restrict__ A, const float* __restrict__ B,
    int M, int K, int Nout, int n_base, int m0,
    float (&acc)[2][8][4], float (&As)[2][128][20], float (&Bs)[2][16][136])
{
    const int tid = threadIdx.x;
    const int lane = tid & 31;
    const int wid = tid >> 5;
    const int warp_m = wid & 3;
    const int warp_n = wid >> 2;

#pragma unroll
    for (int i = 0; i < 2; i++)
#pragma unroll
        for (int j = 0; j < 8; j++)
#pragma unroll
            for (int c = 0; c < 4; c++) acc[i][j][c] = 0.f;

    float4 pa[2], pb[2];

#define LOAD_TILE(K0)                                                         \
    {                                                                         \
        const int k0c_ = (K0);                                                \
        _Pragma("unroll")                                                     \
        for (int _t = 0; _t < 2; _t++) {                                      \
            int j = tid + _t * 256;                                           \
            int r = j >> 2, q = (j & 3) * 4;                                  \
            pa[_t] = (m0 + r < M)                                             \
                ? *(const float4*)&A[(size_t)(m0 + r) * K + k0c_ + q]         \
                : make_float4(0.f, 0.f, 0.f, 0.f);                            \
            int br = j >> 5, c4 = (j & 31) * 4;                               \
            pb[_t] = *(const float4*)&B[(size_t)(k0c_ + br) * Nout + n_base + c4]; \
        }                                                                     \
    }

#define STORE_TILE(BUF)                                                       \
    {                                                                         \
        const int buf_ = (BUF);                                               \
        _Pragma("unroll")                                                     \
        for (int _t = 0; _t < 2; _t++) {                                      \
            int j = tid + _t * 256;                                           \
            int r = j >> 2, q = (j & 3) * 4;                                  \
            As[buf_][r][q + 0] = to_tf32(pa[_t].x);                           \
            As[buf_][r][q + 1] = to_tf32(pa[_t].y);                           \
            As[buf_][r][q + 2] = to_tf32(pa[_t].z);                           \
            As[buf_][r][q + 3] = to_tf32(pa[_t].w);                           \
            int br = j >> 5, c4 = (j & 31) * 4;                               \
            Bs[buf_][br][c4 + 0] = to_tf32(pb[_t].x);                         \
            Bs[buf_][br][c4 + 1] = to_tf32(pb[_t].y);                         \
            Bs[buf_][br][c4 + 2] = to_tf32(pb[_t].z);                         \
            Bs[buf_][br][c4 + 3] = to_tf32(pb[_t].w);                         \
        }                                                                     \
    }

    LOAD_TILE(0);
    STORE_TILE(0);
    __syncthreads();

    const int T = K >> 4;
#pragma unroll 2
    for (int t = 0; t < T; t++) {
        if (t + 1 < T) LOAD_TILE((t + 1) << 4);
        const int b = t & 1;
#pragma unroll
        for (int kk = 0; kk < 16; kk += 8) {
            unsigned bf[8][2];
#pragma unroll
            for (int nt = 0; nt < 8; nt++) {
                int n = warp_n * 64 + nt * 8 + (lane >> 2);
                bf[nt][0] = __float_as_uint(Bs[b][kk + (lane & 3)][n]);
                bf[nt][1] = __float_as_uint(Bs[b][kk + 4 + (lane & 3)][n]);
            }
#pragma unroll
            for (int mt = 0; mt < 2; mt++) {
                int r0 = warp_m * 32 + mt * 16 + (lane >> 2);
                unsigned a0 = __float_as_uint(As[b][r0][kk + (lane & 3)]);
                unsigned a1 = __float_as_uint(As[b][r0 + 8][kk + (lane & 3)]);
                unsigned a2 = __float_as_uint(As[b][r0][kk + 4 + (lane & 3)]);
                unsigned a3 = __float_as_uint(As[b][r0 + 8][kk + 4 + (lane & 3)]);
#pragma unroll
                for (int nt = 0; nt < 8; nt++)
                    mma_tf32(acc[mt][nt], a0, a1, a2, a3, bf[nt][0], bf[nt][1]);
            }
        }
        if (t + 1 < T) STORE_TILE((t + 1) & 1);
        __syncthreads();
    }
#undef LOAD_TILE
#undef STORE_TILE
}

// ---------------------------------------------------------------------------
// proj4 (q/k/v/skip) via tensor cores; q scaled at store.
// ---------------------------------------------------------------------------
__global__ void __launch_bounds__(256)
proj_mma_kernel(const float* __restrict__ A,
                const float* __restrict__ Wq, const float* __restrict__ bq,
                const float* __restrict__ Wk, const float* __restrict__ bk,
                const float* __restrict__ Wv, const float* __restrict__ bv,
                const float* __restrict__ Ws, const float* __restrict__ bs,
                int M)
{
    const float* B; const float* bias; float* C; float scale;
    switch (blockIdx.y) {
        case 0: B = Wq; bias = bq; C = g_q;  scale = QSCALE; break;
        case 1: B = Wk; bias = bk; C = g_k;  scale = 1.f;    break;
        case 2: B = Wv; bias = bv; C = g_v;  scale = 1.f;    break;
        default: B = Ws; bias = bs; C = g_xr; scale = 1.f;   break;
    }
    __shared__ float As[2][128][20];
    __shared__ float Bs[2][16][136];
    float acc[2][8][4];
    const int m0 = blockIdx.x * 128;
    mma_core(A, B, M, DIM, DIM, 0, m0, acc, As, Bs);

    const int lane = threadIdx.x & 31;
    const int wid = threadIdx.x >> 5;
    const int warp_m = wid & 3, warp_n = wid >> 2;
#pragma unroll
    for (int mt = 0; mt < 2; mt++)
#pragma unroll
        for (int h2 = 0; h2 < 2; h2++) {
            int m = m0 + warp_m * 32 + mt * 16 + (lane >> 2) + h2 * 8;
            if (m >= M) continue;
#pragma unroll
            for (int nt = 0; nt < 8; nt++) {
                int col = warp_n * 64 + nt * 8 + (lane & 3) * 2;
                float2 st;
                st.x = (acc[mt][nt][h2 * 2]     + __ldg(&bias[col]))     * scale;
                st.y = (acc[mt][nt][h2 * 2 + 1] + __ldg(&bias[col + 1])) * scale;
                *(float2*)&C[(size_t)m * DIM + col] = st;
            }
        }
}

// ---------------------------------------------------------------------------
// Fused FFN: out = LN( h + relu(h@Wf1+bf1)@Wf2 + bf2 ; g2,b2 )
// ---------------------------------------------------------------------------
#define FFN_SMEM_FLOATS (2 * 128 * 132 + 2 * 16 * 136)

__global__ void __launch_bounds__(256)
ffn_fused_kernel(const float* __restrict__ A, const float* __restrict__ Wf1,
                 const float* __restrict__ bf1, const float* __restrict__ Wf2,
                 const float* __restrict__ bf2, float* __restrict__ C,
                 const float* __restrict__ gamma, const float* __restrict__ betap,
                 int M)
{
    extern __shared__ float sm[];
    float (*H)[132] = (float(*)[132])sm;
    float (*T)[132] = (float(*)[132])(sm + 128 * 132);
    float (*Bs)[16][136] = (float(*)[16][136])(sm + 2 * 128 * 132);

    const int tid = threadIdx.x;
    const int lane = tid & 31;
    const int wid = tid >> 5;
    const int warp_m = wid & 3;
    const int warp_n = wid >> 2;
    const int m0 = blockIdx.x * 128;

#pragma unroll
    for (int t = 0; t < 16; t++) {
        int j = tid + t * 256;
        int r = j >> 5, c4 = (j & 31) * 4;
        float4 v = (m0 + r < M) ? *(const float4*)&A[(size_t)(m0 + r) * DIM + c4]
                                : make_float4(0.f, 0.f, 0.f, 0.f);
        H[r][c4 + 0] = to_tf32(v.x);
        H[r][c4 + 1] = to_tf32(v.y);
        H[r][c4 + 2] = to_tf32(v.z);
        H[r][c4 + 3] = to_tf32(v.w);
    }
    __syncthreads();

    float acc2[2][8][4];
#pragma unroll
    for (int i = 0; i < 2; i++)
#pragma unroll
        for (int j = 0; j < 8; j++)
#pragma unroll
            for (int c = 0; c < 4; c++) acc2[i][j][c] = 0.f;

    float4 pbv[2];

#define LOADB1(CH_, T0)                                                       \
    {                                                                         \
        _Pragma("unroll")                                                     \
        for (int _t = 0; _t < 2; _t++) {                                      \
            int j = tid + _t * 256;                                           \
            int br = j >> 5, c4 = (j & 31) * 4;                               \
            pbv[_t] = *(const float4*)&Wf1[(size_t)((T0) * 16 + br) * 512     \
                                           + (CH_) * 128 + c4];               \
        }                                                                     \
    }
#define LOADB2(CH_, T0)                                                       \
    {                                                                         \
        _Pragma("unroll")                                                     \
        for (int _t = 0; _t < 2; _t++) {                                      \
            int j = tid + _t * 256;                                           \
            int br = j >> 5, c4 = (j & 31) * 4;                               \
            pbv[_t] = *(const float4*)&Wf2[(size_t)((CH_) * 128 + (T0) * 16 + br) * 128 + c4]; \
        }                                                                     \
    }
#define STOREB(BUF)                                                           \
    {                                                                         \
        const int buf_ = (BUF);                                               \
        _Pragma("unroll")                                                     \
        for (int _t = 0; _t < 2; _t++) {                                      \
            int j = tid + _t * 256;                                           \
            int br = j >> 5, c4 = (j & 31) * 4;                               \
            Bs[buf_][br][c4 + 0] = to_tf32(pbv[_t].x);                        \
            Bs[buf_][br][c4 + 1] = to_tf32(pbv[_t].y);                        \
            Bs[buf_][br][c4 + 2] = to_tf32(pbv[_t].z);                        \
            Bs[buf_][br][c4 + 3] = to_tf32(pbv[_t].w);                        \
        }                                                                     \
    }

#define GEMM_STEP(ACC, ASRC, B_, KGLOB)                                       \
    {                                                                         \
        _Pragma("unroll")                                                     \
        for (int kk0 = 0; kk0 < 16; kk0 += 8) {                               \
            int kk = (KGLOB) + kk0;                                           \
            unsigned bf[8][2];                                                \
            _Pragma("unroll")                                                 \
            for (int nt = 0; nt < 8; nt++) {                                  \
                int n = warp_n * 64 + nt * 8 + (lane >> 2);                   \
                bf[nt][0] = __float_as_uint(Bs[B_][kk0 + (lane & 3)][n]);     \
                bf[nt][1] = __float_as_uint(Bs[B_][kk0 + 4 + (lane & 3)][n]); \
            }                                                                 \
            _Pragma("unroll")                                                 \
            for (int mt = 0; mt < 2; mt++) {                                  \
                int r0 = warp_m * 32 + mt * 16 + (lane >> 2);                 \
                unsigned a0 = __float_as_uint(ASRC[r0][kk + (lane & 3)]);     \
                unsigned a1 = __float_as_uint(ASRC[r0 + 8][kk + (lane & 3)]); \
                unsigned a2 = __float_as_uint(ASRC[r0][kk + 4 + (lane & 3)]); \
                unsigned a3 = __float_as_uint(ASRC[r0 + 8][kk + 4 + (lane & 3)]); \
                _Pragma("unroll")                                             \
                for (int nt = 0; nt < 8; nt++)                                \
                    mma_tf32(ACC[mt][nt], a0, a1, a2, a3, bf[nt][0], bf[nt][1]); \
            }                                                                 \
        }                                                                     \
    }

#pragma unroll 1
    for (int c = 0; c < 4; c++) {
        float acc1[2][8][4];
#pragma unroll
        for (int i = 0; i < 2; i++)
#pragma unroll
            for (int j = 0; j < 8; j++)
#pragma unroll
                for (int cc = 0; cc < 4; cc++) acc1[i][j][cc] = 0.f;

        LOADB1(c, 0);
        STOREB(0);
        __syncthreads();
#pragma unroll
        for (int t = 0; t < 8; t++) {
            if (t < 7) LOADB1(c, t + 1);
            GEMM_STEP(acc1, H, t & 1, t * 16);
            if (t < 7) STOREB((t + 1) & 1);
            __syncthreads();
        }

#pragma unroll
        for (int mt = 0; mt < 2; mt++)
#pragma unroll
            for (int h2 = 0; h2 < 2; h2++) {
                int row = warp_m * 32 + mt * 16 + (lane >> 2) + h2 * 8;
#pragma unroll
                for (int nt = 0; nt < 8; nt++) {
                    int col = warp_n * 64 + nt * 8 + (lane & 3) * 2;
                    int gcol = c * 128 + col;
                    float t0 = fmaxf(acc1[mt][nt][h2 * 2]     + __ldg(&bf1[gcol]), 0.f);
                    float t1 = fmaxf(acc1[mt][nt][h2 * 2 + 1] + __ldg(&bf1[gcol + 1]), 0.f);
                    T[row][col]     = to_tf32(t0);
                    T[row][col + 1] = to_tf32(t1);
                }
            }

        LOADB2(c, 0);
        STOREB(0);
        __syncthreads();
#pragma unroll
        for (int t = 0; t < 8; t++) {
            if (t < 7) LOADB2(c, t + 1);
            GEMM_STEP(acc2, T, t & 1, t * 16);
            if (t < 7) STOREB((t + 1) & 1);
            __syncthreads();
        }
    }
#undef LOADB1
#undef LOADB2
#undef STOREB
#undef GEMM_STEP

    float (*pr)[2] = (float(*)[2])H;
    float mu[2][2];
#pragma unroll
    for (int mt = 0; mt < 2; mt++)
#pragma unroll
        for (int h2 = 0; h2 < 2; h2++) {
            int row = warp_m * 32 + mt * 16 + (lane >> 2) + h2 * 8;
            int m = m0 + row;
            float s = 0.f;
#pragma unroll
            for (int nt = 0; nt < 8; nt++) {
                int col = warp_n * 64 + nt * 8 + (lane & 3) * 2;
                float r0 = (m < M) ? __ldg(&A[(size_t)m * DIM + col])     : 0.f;
                float r1 = (m < M) ? __ldg(&A[(size_t)m * DIM + col + 1]) : 0.f;
                float t0 = acc2[mt][nt][h2 * 2]     + __ldg(&bf2[col])     + r0;
                float t1 = acc2[mt][nt][h2 * 2 + 1] + __ldg(&bf2[col + 1]) + r1;
                acc2[mt][nt][h2 * 2] = t0;
                acc2[mt][nt][h2 * 2 + 1] = t1;
                s += t0 + t1;
            }
            s += __shfl_xor_sync(0xffffffffu, s, 1);
            s += __shfl_xor_sync(0xffffffffu, s, 2);
            if ((lane & 3) == 0) pr[row][warp_n] = s;
        }
    __syncthreads();
#pragma unroll
    for (int mt = 0; mt < 2; mt++)
#pragma unroll
        for (int h2 = 0; h2 < 2; h2++) {
            int row = warp_m * 32 + mt * 16 + (lane >> 2) + h2 * 8;
            mu[mt][h2] = (pr[row][0] + pr[row][1]) * (1.0f / 128.0f);
        }
    __syncthreads();
#pragma unroll
    for (int mt = 0; mt < 2; mt++)
#pragma unroll
        for (int h2 = 0; h2 < 2; h2++) {
            int row = warp_m * 32 + mt * 16 + (lane >> 2) + h2 * 8;
            float vs = 0.f;
#pragma unroll
            for (int nt = 0; nt < 8; nt++) {
                float d0 = acc2[mt][nt][h2 * 2]     - mu[mt][h2];
                float d1 = acc2[mt][nt][h2 * 2 + 1] - mu[mt][h2];
                vs += d0 * d0 + d1 * d1;
            }
            vs += __shfl_xor_sync(0xffffffffu, vs, 1);
            vs += __shfl_xor_sync(0xffffffffu, vs, 2);
            if ((lane & 3) == 0) pr[row][warp_n] = vs;
        }
    __syncthreads();
#pragma unroll
    for (int mt = 0; mt < 2; mt++)
#pragma unroll
        for (int h2 = 0; h2 < 2; h2++) {
            int row = warp_m * 32 + mt * 16 + (lane >> 2) + h2 * 8;
            int m = m0 + row;
            if (m >= M) continue;
            float var = (pr[row][0] + pr[row][1]) * (1.0f / 128.0f);
            float inv = rsqrtf(var + 1e-5f);
#pragma unroll
            for (int nt = 0; nt < 8; nt++) {
                int col = warp_n * 64 + nt * 8 + (lane & 3) * 2;
                float2 st;
                st.x = (acc2[mt][nt][h2 * 2]     - mu[mt][h2]) * inv * __ldg(&gamma[col])     + __ldg(&betap[col]);
                st.y = (acc2[mt][nt][h2 * 2 + 1] - mu[mt][h2]) * inv * __ldg(&gamma[col + 1]) + __ldg(&betap[col + 1]);
                *(float2*)&C[(size_t)m * DIM + col] = st;
            }
        }
}

// ---------------------------------------------------------------------------
// qwe precompute
// ---------------------------------------------------------------------------
__global__ void __launch_bounds__(256)
qwe_kernel(const float* __restrict__ We, const float* __restrict__ be, int N)
{
    __shared__ float sWe[EDIM * DIM];
    __shared__ float sq[4][DIM];
    __shared__ float sbe[DIM];
    int tid = threadIdx.x;
    for (int i = tid; i < EDIM * DIM; i += 256) sWe[i] = We[i];
    if (tid < DIM) sbe[tid] = be[tid];
    int n0 = blockIdx.x * 4;
    for (int i = tid; i < 4 * DIM; i += 256) {
        int nn = i >> 7, c = i & 127;
        sq[nn][c] = (n0 + nn < N) ? g_q[(size_t)(n0 + nn) * DIM + c] : 0.f;
    }
    __syncthreads();
    int nn = tid >> 6, r = tid & 63, h = r >> 4, i = r & 15;
    int n = n0 + nn;
    if (n >= N) return;
    float a = 0.f;
#pragma unroll
    for (int c = 0; c < 32; c++)
        a = fmaf(sq[nn][h * 32 + c], sWe[i * DIM + h * 32 + c], a);
    g_qwe[(size_t)n * 64 + h * 16 + i] = a;
    if (i == 0) {
        float qb = 0.f;
#pragma unroll
        for (int c = 0; c < 32; c++)
            qb = fmaf(sq[nn][h * 32 + c], sbe[h * 32 + c], qb);
        g_qbe[n * 4 + h] = qb;
    }
}

// ---------------------------------------------------------------------------
// Warp-per-node attention: dynamic work queue + 4-edge pipeline + beta + LN1.
// ---------------------------------------------------------------------------
__global__ void __launch_bounds__(256)
node_attn_kernel(const float* __restrict__ We, const float* __restrict__ be,
                 const float* __restrict__ x,  const float* __restrict__ Wbeta,
                 const float* __restrict__ g1, const float* __restrict__ b1,
                 int N)
{
    __shared__ float sWe[EDIM][DIM];
    __shared__ float sbe[DIM];
    for (int i = threadIdx.x; i < EDIM * DIM; i += 256)
        ((float*)sWe)[i] = We[i];
    if (threadIdx.x < DIM) sbe[threadIdx.x] = be[threadIdx.x];
    __syncthreads();

    const int lane = threadIdx.x & 31;
    const int g = lane >> 3;
    const int l8 = lane & 7;
    const int ch0 = g * 32 + l8 * 4;

    for (;;) {
        int n;
        if (lane == 0) n = atomicAdd(&g_work, 1);
        n = __shfl_sync(0xffffffffu, n, 0);
        if (n >= N) break;

        float4 q4 = *(const float4*)&g_q[(size_t)n * DIM + ch0];
        float2 qwe2 = *(const float2*)&g_qwe[(size_t)n * 64 + g * 16 + 2 * l8];
        float qbe = g_qbe[n * 4 + g];

        float4 acc = make_float4(0.f, 0.f, 0.f, 0.f);
        float s0 = 0.f, s1 = 0.f, den = 0.f;

        int beg = g_rowptr[n], end = g_rowptr[n + 1];
        int p = beg;
        for (; p + 4 <= end; p += 4) {
            int sA = __ldg(&g_ssrc[p]);
            int sB = __ldg(&g_ssrc[p + 1]);
            int sC = __ldg(&g_ssrc[p + 2]);
            int sD = __ldg(&g_ssrc[p + 3]);
            float4 kA = *(const float4*)&g_k[(size_t)sA * DIM + ch0];
            float4 kB = *(const float4*)&g_k[(size_t)sB * DIM + ch0];
            float4 kC = *(const float4*)&g_k[(size_t)sC * DIM + ch0];
            float4 kD = *(const float4*)&g_k[(size_t)sD * DIM + ch0];
            float4 vA = *(const float4*)&g_v[(size_t)sA * DIM + ch0];
            float4 vB = *(const float4*)&g_v[(size_t)sB * DIM + ch0];
            float4 vC = *(const float4*)&g_v[(size_t)sC * DIM + ch0];
            float4 vD = *(const float4*)&g_v[(size_t)sD * DIM + ch0];
            float2 aA = *(const float2*)&g_eperm[(size_t)p * EDIM + 2 * l8];
            float2 aB = *(const float2*)&g_eperm[(size_t)(p + 1) * EDIM + 2 * l8];
            float2 aC = *(const float2*)&g_eperm[(size_t)(p + 2) * EDIM + 2 * l8];
            float2 aD = *(const float2*)&g_eperm[(size_t)(p + 3) * EDIM + 2 * l8];

            float pA = q4.x * kA.x + q4.y * kA.y + q4.z * kA.z + q4.w * kA.w
                     + aA.x * qwe2.x + aA.y * qwe2.y;
            float pB = q4.x * kB.x + q4.y * kB.y + q4.z * kB.z + q4.w * kB.w
                     + aB.x * qwe2.x + aB.y * qwe2.y;
            float pC = q4.x * kC.x + q4.y * kC.y + q4.z * kC.z + q4.w * kC.w
                     + aC.x * qwe2.x + aC.y * qwe2.y;
            float pD = q4.x * kD.x + q4.y * kD.y + q4.z * kD.z + q4.w * kD.w
                     + aD.x * qwe2.x + aD.y * qwe2.y;
            pA += __shfl_xor_sync(0xffffffffu, pA, 1);
            pB += __shfl_xor_sync(0xffffffffu, pB, 1);
            pC += __shfl_xor_sync(0xffffffffu, pC, 1);
            pD += __shfl_xor_sync(0xffffffffu, pD, 1);
            pA += __shfl_xor_sync(0xffffffffu, pA, 2);
            pB += __shfl_xor_sync(0xffffffffu, pB, 2);
            pC += __shfl_xor_sync(0xffffffffu, pC, 2);
            pD += __shfl_xor_sync(0xffffffffu, pD, 2);
            pA += __shfl_xor_sync(0xffffffffu, pA, 4);
            pB += __shfl_xor_sync(0xffffffffu, pB, 4);
            pC += __shfl_xor_sync(0xffffffffu, pC, 4);
            pD += __shfl_xor_sync(0xffffffffu, pD, 4);
            float eA = __expf(pA + qbe);
            float eB = __expf(pB + qbe);
            float eC = __expf(pC + qbe);
            float eD = __expf(pD + qbe);
            den += eA;
            acc.x = fmaf(eA, vA.x, acc.x); acc.y = fmaf(eA, vA.y, acc.y);
            acc.z = fmaf(eA, vA.z, acc.z); acc.w = fmaf(eA, vA.w, acc.w);
            s0 = fmaf(eA, aA.x, s0); s1 = fmaf(eA, aA.y, s1);
            den += eB;
            acc.x = fmaf(eB, vB.x, acc.x); acc.y = fmaf(eB, vB.y, acc.y);
            acc.z = fmaf(eB, vB.z, acc.z); acc.w = fmaf(eB, vB.w, acc.w);
            s0 = fmaf(eB, aB.x, s0); s1 = fmaf(eB, aB.y, s1);
            den += eC;
            acc.x = fmaf(eC, vC.x, acc.x); acc.y = fmaf(eC, vC.y, acc.y);
            acc.z = fmaf(eC, vC.z, acc.z); acc.w = fmaf(eC, vC.w, acc.w);
            s0 = fmaf(eC, aC.x, s0); s1 = fmaf(eC, aC.y, s1);
            den += eD;
            acc.x = fmaf(eD, vD.x, acc.x); acc.y = fmaf(eD, vD.y, acc.y);
            acc.z = fmaf(eD, vD.z, acc.z); acc.w = fmaf(eD, vD.w, acc.w);
            s0 = fmaf(eD, aD.x, s0); s1 = fmaf(eD, aD.y, s1);
        }
        for (; p < end; p++) {
            int sA = __ldg(&g_ssrc[p]);
            float2 aA = *(const float2*)&g_eperm[(size_t)p * EDIM + 2 * l8];
            float4 kA = *(const float4*)&g_k[(size_t)sA * DIM + ch0];
            float4 vA = *(const float4*)&g_v[(size_t)sA * DIM + ch0];
            float pp = q4.x * kA.x + q4.y * kA.y + q4.z * kA.z + q4.w * kA.w
                     + aA.x * qwe2.x + aA.y * qwe2.y;
            pp += __shfl_xor_sync(0xffffffffu, pp, 1);
            pp += __shfl_xor_sync(0xffffffffu, pp, 2);
            pp += __shfl_xor_sync(0xffffffffu, pp, 4);
            float ea = __expf(pp + qbe);
            den += ea;
            acc.x = fmaf(ea, vA.x, acc.x); acc.y = fmaf(ea, vA.y, acc.y);
            acc.z = fmaf(ea, vA.z, acc.z); acc.w = fmaf(ea, vA.w, acc.w);
            s0 = fmaf(ea, aA.x, s0); s1 = fmaf(ea, aA.y, s1);
        }

        float4 ev;
        ev.x = den * sbe[ch0];
        ev.y = den * sbe[ch0 + 1];
        ev.z = den * sbe[ch0 + 2];
        ev.w = den * sbe[ch0 + 3];
#pragma unroll
        for (int jj = 0; jj < 8; jj++) {
            int srcl = (g << 3) | jj;
            float sj0 = __shfl_sync(0xffffffffu, s0, srcl);
            float sj1 = __shfl_sync(0xffffffffu, s1, srcl);
            float4 w0 = *(const float4*)&sWe[2 * jj][ch0];
            float4 w1 = *(const float4*)&sWe[2 * jj + 1][ch0];
            ev.x += sj0 * w0.x + sj1 * w1.x;
            ev.y += sj0 * w0.y + sj1 * w1.y;
            ev.z += sj0 * w0.z + sj1 * w1.z;
            ev.w += sj0 * w0.w + sj1 * w1.w;
        }
        float rden = 1.0f / (den + 1e-16f);
        float o[4] = {(acc.x + ev.x) * rden, (acc.y + ev.y) * rden,
                      (acc.z + ev.z) * rden, (acc.w + ev.w) * rden};

        float4 xr4 = *(const float4*)&g_xr[(size_t)n * DIM + ch0];
        float4 wb0 = *(const float4*)&Wbeta[ch0];
        float4 wb1 = *(const float4*)&Wbeta[DIM + ch0];
        float4 wb2 = *(const float4*)&Wbeta[2 * DIM + ch0];
        float xr[4] = {xr4.x, xr4.y, xr4.z, xr4.w};
        float z = wb0.x * o[0] + wb1.x * xr[0] + wb2.x * (o[0] - xr[0])
                + wb0.y * o[1] + wb1.y * xr[1] + wb2.y * (o[1] - xr[1])
                + wb0.z * o[2] + wb1.z * xr[2] + wb2.z * (o[2] - xr[2])
                + wb0.w * o[3] + wb1.w * xr[3] + wb2.w * (o[3] - xr[3]);
        z = warpSum(z);
        float beta = 1.0f / (1.0f + __expf(-z));

        float4 xv = *(const float4*)&x[(size_t)n * DIM + ch0];
        float xx[4] = {xv.x, xv.y, xv.z, xv.w};
        float tv[4], ts = 0.f;
#pragma unroll
        for (int c = 0; c < 4; c++) {
            tv[c] = xx[c] + beta * xr[c] + (1.0f - beta) * o[c];
            ts += tv[c];
        }
        float mu = warpSum(ts) * (1.0f / 128.0f);
        float vs = 0.f;
#pragma unroll
        for (int c = 0; c < 4; c++) { tv[c] -= mu; vs += tv[c] * tv[c]; }
        float var = warpSum(vs) * (1.0f / 128.0f);
        float inv = rsqrtf(var + 1e-5f);

        float4 gg = *(const float4*)&g1[ch0];
        float4 bb = *(const float4*)&b1[ch0];
        float4 st;
        st.x = tv[0] * inv * gg.x + bb.x;
        st.y = tv[1] * inv * gg.y + bb.y;
        st.z = tv[2] * inv * gg.z + bb.z;
        st.w = tv[3] * inv * gg.w + bb.w;
        *(float4*)&g_h[(size_t)n * DIM + ch0] = st;
    }
}

// ---------------------------------------------------------------------------
// Launch: explicit non-blocking streams for both branches.
// ---------------------------------------------------------------------------
extern "C" void kernel_launch(void* const* d_in, const int* in_sizes, int n_in,
                              void* d_out, int out_size)
{
    const float* x      = (const float*)d_in[0];
    const void*  eidx   = d_in[1];
    const float* eattr  = (const float*)d_in[2];
    const float* Wq     = (const float*)d_in[3];
    const float* bq     = (const float*)d_in[4];
    const float* Wk     = (const float*)d_in[5];
    const float* bk     = (const float*)d_in[6];
    const float* Wv     = (const float*)d_in[7];
    const float* bv     = (const float*)d_in[8];
    const float* We     = (const float*)d_in[9];
    const float* be     = (const float*)d_in[10];
    const float* Ws     = (const float*)d_in[11];
    const float* bs     = (const float*)d_in[12];
    const float* Wbeta  = (const float*)d_in[13];
    const float* g1     = (const float*)d_in[14];
    const float* b1     = (const float*)d_in[15];
    const float* Wf1    = (const float*)d_in[16];
    const float* bf1    = (const float*)d_in[17];
    const float* Wf2    = (const float*)d_in[18];
    const float* bf2    = (const float*)d_in[19];
    const float* g2     = (const float*)d_in[20];
    const float* b2     = (const float*)d_in[21];

    const int N = in_sizes[0] / DIM;
    const int E = in_sizes[1] / 2;

    float *h;
    int *cnt, *work;
    cudaGetSymbolAddress((void**)&h, g_h);
    cudaGetSymbolAddress((void**)&cnt, g_cnt);
    cudaGetSymbolAddress((void**)&work, g_work);

    static cudaStream_t s1 = nullptr, s2 = nullptr;
    static cudaEvent_t evFork = nullptr, evCsr = nullptr, evProj = nullptr;
    if (!s1) {
        cudaStreamCreateWithFlags(&s1, cudaStreamNonBlocking);
        cudaStreamCreateWithFlags(&s2, cudaStreamNonBlocking);
        cudaEventCreateWithFlags(&evFork, cudaEventDisableTiming);
        cudaEventCreateWithFlags(&evCsr, cudaEventDisableTiming);
        cudaEventCreateWithFlags(&evProj, cudaEventDisableTiming);
        cudaFuncSetAttribute(ffn_fused_kernel,
                             cudaFuncAttributeMaxDynamicSharedMemorySize,
                             FFN_SMEM_FLOATS * 4);
    }

    const int nb = (N + 1023) / 1024;
    const int gm = (N + 127) / 128;

    // fork from caller stream 0
    cudaEventRecord(evFork, 0);
    cudaStreamWaitEvent(s1, evFork, 0);
    cudaStreamWaitEvent(s2, evFork, 0);

    // branch 1 (s1): CSR chain
    cudaMemsetAsync(cnt, 0, (size_t)N * sizeof(int), s1);
    detect_idx_kernel<<<1, 32, 0, s1>>>((const int*)eidx);
    convert_idx_kernel<<<(E + 255) / 256, 256, 0, s1>>>(eidx, E);
    scanA_kernel<<<nb, 1024, 0, s1>>>(N);
    scanB_kernel<<<1, 32, 0, s1>>>(nb, N, E);
    scanC_kernel<<<nb, 1024, 0, s1>>>(N);
    scatter_kernel<<<(E + 255) / 256, 256, 0, s1>>>(E);
    permute_eattr_kernel<<<(E * 4 + 255) / 256, 256, 0, s1>>>(eattr, E);
    cudaEventRecord(evCsr, s1);

    // branch 2 (s2): projections + qwe + work-counter reset
    cudaMemsetAsync(work, 0, sizeof(int), s2);
    dim3 gproj(gm, 4);
    proj_mma_kernel<<<gproj, 256, 0, s2>>>(x, Wq, bq, Wk, bk, Wv, bv, Ws, bs, N);
    qwe_kernel<<<(N + 3) / 4, 256, 0, s2>>>(We, be, N);
    cudaEventRecord(evProj, s2);

    // join into stream 0
    cudaStreamWaitEvent(0, evCsr, 0);
    cudaStreamWaitEvent(0, evProj, 0);

    node_attn_kernel<<<1184, 256>>>(We, be, x, Wbeta, g1, b1, N);

    ffn_fused_kernel<<<gm, 256, FFN_SMEM_FLOATS * 4>>>(
        h, Wf1, bf1, Wf2, bf2, (float*)d_out, g2, b2, N);
}

// round 13
// speedup vs baseline: 1.1645x; 1.0783x over previous
#include <cuda_runtime.h>
#include <cuda_bf16.h>
#include <cuda_fp16.h>
#include <math.h>

#define NMAX 50000
#define EMAX 800000
#define DIM  128
#define HEADS 4
#define CH   32
#define EDIM 16
#define QSCALE 0.17677669529663687f   // 1/sqrt(32)

// ---------------------------------------------------------------------------
// Scratch
// ---------------------------------------------------------------------------
__device__ float  g_q[NMAX * DIM];
__device__ __half g_kh[NMAX * DIM];
__device__ __half g_vh[NMAX * DIM];
__device__ float  g_xr[NMAX * DIM];
__device__ float  g_h[NMAX * DIM];
__device__ float  g_qwe[(size_t)NMAX * 64];
__device__ float  g_qbe[NMAX * 4];
__device__ __half g_eph[(size_t)EMAX * EDIM];
__device__ int    g_src[EMAX];
__device__ int    g_dst[EMAX];
__device__ int    g_ssrc[EMAX];
__device__ int    g_eid[EMAX];
__device__ int    g_cnt[NMAX];
__device__ int    g_rowptr[NMAX + 1];
__device__ int    g_woff[NMAX];
__device__ int    g_bsum[64];
__device__ int    g_boff[64];
__device__ int    g_idx64;
__device__ int    g_work;

// ---------------------------------------------------------------------------
// Helpers
// ---------------------------------------------------------------------------
__device__ __forceinline__ float warpSum(float v) {
#pragma unroll
    for (int off = 16; off; off >>= 1)
        v += __shfl_xor_sync(0xffffffffu, v, off);
    return v;
}

__device__ __forceinline__ float to_tf32(float x) {
    float r;
    asm("cvt.rna.tf32.f32 %0, %1;" : "=f"(r) : "f"(x));
    return r;
}

__device__ __forceinline__ void mma_tf32(float c[4],
                                         unsigned a0, unsigned a1, unsigned a2, unsigned a3,
                                         unsigned b0, unsigned b1) {
    asm volatile(
        "mma.sync.aligned.m16n8k8.row.col.f32.tf32.tf32.f32 "
        "{%0,%1,%2,%3},{%4,%5,%6,%7},{%8,%9},{%0,%1,%2,%3};"
        : "+f"(c[0]), "+f"(c[1]), "+f"(c[2]), "+f"(c[3])
        : "r"(a0), "r"(a1), "r"(a2), "r"(a3), "r"(b0), "r"(b1));
}

// ---------------------------------------------------------------------------
// Index detect / convert (+fused histogram)
// ---------------------------------------------------------------------------
__global__ void detect_idx_kernel(const int* raw) {
    int t = threadIdx.x;
    int hi_nz = 0, lo_nz = 0;
    for (int i = t; i < 256; i += 32) {
        if (raw[2 * i + 1] != 0) hi_nz = 1;
        if (raw[2 * i] != 0) lo_nz = 1;
    }
    unsigned hi = __ballot_sync(0xffffffffu, hi_nz);
    unsigned lo = __ballot_sync(0xffffffffu, lo_nz);
    if (t == 0) g_idx64 = (hi == 0u && lo != 0u) ? 1 : 0;
}

__global__ void convert_idx_kernel(const void* raw, int E) {
    int i = blockIdx.x * blockDim.x + threadIdx.x;
    if (i >= E) return;
    int s, d;
    if (g_idx64) {
        const long long* p = (const long long*)raw;
        s = (int)p[i];
        d = (int)p[E + i];
    } else {
        const int* p = (const int*)raw;
        s = p[i];
        d = p[E + i];
    }
    g_src[i] = s;
    g_dst[i] = d;
    atomicAdd(&g_cnt[d], 1);
}

// ---------------------------------------------------------------------------
// 3-phase exclusive scan
// ---------------------------------------------------------------------------
__global__ void __launch_bounds__(1024)
scanA_kernel(int N) {
    __shared__ int wsum[32];
    int t = threadIdx.x;
    int i = blockIdx.x * 1024 + t;
    int v = (i < N) ? g_cnt[i] : 0;
    int inc = v;
#pragma unroll
    for (int off = 1; off < 32; off <<= 1) {
        int u = __shfl_up_sync(0xffffffffu, inc, off);
        if ((t & 31) >= off) inc += u;
    }
    if ((t & 31) == 31) wsum[t >> 5] = inc;
    __syncthreads();
    if (t < 32) {
        int w = wsum[t];
        int wi = w;
#pragma unroll
        for (int off = 1; off < 32; off <<= 1) {
            int u = __shfl_up_sync(0xffffffffu, wi, off);
            if (t >= off) wi += u;
        }
        wsum[t] = wi - w;
    }
    __syncthreads();
    int exc = inc - v + wsum[t >> 5];
    if (i < N) g_rowptr[i] = exc;
    if (t == 1023) g_bsum[blockIdx.x] = exc + v;
}

__global__ void scanB_kernel(int nb, int N, int E) {
    int lane = threadIdx.x;
    int v0 = (lane < nb) ? g_bsum[lane] : 0;
    int v1 = (32 + lane < nb) ? g_bsum[32 + lane] : 0;
    int i0 = v0, i1 = v1;
#pragma unroll
    for (int off = 1; off < 32; off <<= 1) {
        int u = __shfl_up_sync(0xffffffffu, i0, off);
        if (lane >= off) i0 += u;
        int u2 = __shfl_up_sync(0xffffffffu, i1, off);
        if (lane >= off) i1 += u2;
    }
    int tot0 = __shfl_sync(0xffffffffu, i0, 31);
    i1 += tot0;
    g_boff[lane] = i0 - v0;
    g_boff[32 + lane] = i1 - v1;
    if (lane == 0) g_rowptr[N] = E;
}

__global__ void __launch_bounds__(1024)
scanC_kernel(int N) {
    int i = blockIdx.x * 1024 + threadIdx.x;
    if (i < N) {
        int r = g_rowptr[i] + g_boff[blockIdx.x];
        g_rowptr[i] = r;
        g_woff[i] = r;
    }
}

__global__ void scatter_kernel(int E) {
    int i = blockIdx.x * blockDim.x + threadIdx.x;
    if (i >= E) return;
    int d = g_dst[i];
    int pos = atomicAdd(&g_woff[d], 1);
    g_ssrc[pos] = g_src[i];
    g_eid[pos] = i;
}

// permute eattr into CSR order + convert to half
__global__ void __launch_bounds__(256)
permute_eattr_kernel(const float* __restrict__ eattr, int E) {
    int i = blockIdx.x * blockDim.x + threadIdx.x;
    if (i >= E * 4) return;
    int p = i >> 2, q = (i & 3) * 4;
    int e = g_eid[p];
    float4 v = *(const float4*)&eattr[(size_t)e * EDIM + q];
    __half2 h0 = __floats2half2_rn(v.x, v.y);
    __half2 h1 = __floats2half2_rn(v.z, v.w);
    *(__half2*)&g_eph[(size_t)p * EDIM + q]     = h0;
    *(__half2*)&g_eph[(size_t)p * EDIM + q + 2] = h1;
}

// ---------------------------------------------------------------------------
// TF32 MMA core: BK=16, double-buffered smem, ONE sync per k-tile.
// ---------------------------------------------------------------------------
__device__ __forceinline__ void mma_core(
    const float* __restrict__ A, const float* __restrict__ B,
    int M, int K, int Nout, int n_base, int m0,
    float (&acc)[2][8][4], float (&As)[2][128][20], float (&Bs)[2][16][136])
{
    const int tid = threadIdx.x;
    const int lane = tid & 31;
    const int wid = tid >> 5;
    const int warp_m = wid & 3;
    const int warp_n = wid >> 2;

#pragma unroll
    for (int i = 0; i < 2; i++)
#pragma unroll
        for (int j = 0; j < 8; j++)
#pragma unroll
            for (int c = 0; c < 4; c++) acc[i][j][c] = 0.f;

    float4 pa[2], pb[2];

#define LOAD_TILE(K0)                                                         \
    {                                                                         \
        const int k0c_ = (K0);                                                \
        _Pragma("unroll")                                                     \
        for (int _t = 0; _t < 2; _t++) {                                      \
            int j = tid + _t * 256;                                           \
            int r = j >> 2, q = (j & 3) * 4;                                  \
            pa[_t] = (m0 + r < M)                                             \
                ? *(const float4*)&A[(size_t)(m0 + r) * K + k0c_ + q]         \
                : make_float4(0.f, 0.f, 0.f, 0.f);                            \
            int br = j >> 5, c4 = (j & 31) * 4;                               \
            pb[_t] = *(const float4*)&B[(size_t)(k0c_ + br) * Nout + n_base + c4]; \
        }                                                                     \
    }

#define STORE_TILE(BUF)                                                       \
    {                                                                         \
        const int buf_ = (BUF);                                               \
        _Pragma("unroll")                                                     \
        for (int _t = 0; _t < 2; _t++) {                                      \
            int j = tid + _t * 256;                                           \
            int r = j >> 2, q = (j & 3) * 4;                                  \
            As[buf_][r][q + 0] = to_tf32(pa[_t].x);                           \
            As[buf_][r][q + 1] = to_tf32(pa[_t].y);                           \
            As[buf_][r][q + 2] = to_tf32(pa[_t].z);                           \
            As[buf_][r][q + 3] = to_tf32(pa[_t].w);                           \
            int br = j >> 5, c4 = (j & 31) * 4;                               \
            Bs[buf_][br][c4 + 0] = to_tf32(pb[_t].x);                         \
            Bs[buf_][br][c4 + 1] = to_tf32(pb[_t].y);                         \
            Bs[buf_][br][c4 + 2] = to_tf32(pb[_t].z);                         \
            Bs[buf_][br][c4 + 3] = to_tf32(pb[_t].w);                         \
        }                                                                     \
    }

    LOAD_TILE(0);
    STORE_TILE(0);
    __syncthreads();

    const int T = K >> 4;
#pragma unroll 2
    for (int t = 0; t < T; t++) {
        if (t + 1 < T) LOAD_TILE((t + 1) << 4);
        const int b = t & 1;
#pragma unroll
        for (int kk = 0; kk < 16; kk += 8) {
            unsigned bf[8][2];
#pragma unroll
            for (int nt = 0; nt < 8; nt++) {
                int n = warp_n * 64 + nt * 8 + (lane >> 2);
                bf[nt][0] = __float_as_uint(Bs[b][kk + (lane & 3)][n]);
                bf[nt][1] = __float_as_uint(Bs[b][kk + 4 + (lane & 3)][n]);
            }
#pragma unroll
            for (int mt = 0; mt < 2; mt++) {
                int r0 = warp_m * 32 + mt * 16 + (lane >> 2);
                unsigned a0 = __float_as_uint(As[b][r0][kk + (lane & 3)]);
                unsigned a1 = __float_as_uint(As[b][r0 + 8][kk + (lane & 3)]);
                unsigned a2 = __float_as_uint(As[b][r0][kk + 4 + (lane & 3)]);
                unsigned a3 = __float_as_uint(As[b][r0 + 8][kk + 4 + (lane & 3)]);
#pragma unroll
                for (int nt = 0; nt < 8; nt++)
                    mma_tf32(acc[mt][nt], a0, a1, a2, a3, bf[nt][0], bf[nt][1]);
            }
        }
        if (t + 1 < T) STORE_TILE((t + 1) & 1);
        __syncthreads();
    }
#undef LOAD_TILE
#undef STORE_TILE
}

// ---------------------------------------------------------------------------
// proj4 (q/k/v/skip): q,xr stored fp32; k,v stored fp16.
// ---------------------------------------------------------------------------
__global__ void __launch_bounds__(256)
proj_mma_kernel(const float* __restrict__ A,
                const float* __restrict__ Wq, const float* __restrict__ bq,
                const float* __restrict__ Wk, const float* __restrict__ bk,
                const float* __restrict__ Wv, const float* __restrict__ bv,
                const float* __restrict__ Ws, const float* __restrict__ bs,
                int M)
{
    const float* B; const float* bias; float* Cf; __half* Ch; float scale;
    switch (blockIdx.y) {
        case 0: B = Wq; bias = bq; Cf = g_q;  Ch = nullptr; scale = QSCALE; break;
        case 1: B = Wk; bias = bk; Cf = nullptr; Ch = g_kh; scale = 1.f;   break;
        case 2: B = Wv; bias = bv; Cf = nullptr; Ch = g_vh; scale = 1.f;   break;
        default: B = Ws; bias = bs; Cf = g_xr; Ch = nullptr; scale = 1.f;  break;
    }
    __shared__ float As[2][128][20];
    __shared__ float Bs[2][16][136];
    float acc[2][8][4];
    const int m0 = blockIdx.x * 128;
    mma_core(A, B, M, DIM, DIM, 0, m0, acc, As, Bs);

    const int lane = threadIdx.x & 31;
    const int wid = threadIdx.x >> 5;
    const int warp_m = wid & 3, warp_n = wid >> 2;
#pragma unroll
    for (int mt = 0; mt < 2; mt++)
#pragma unroll
        for (int h2 = 0; h2 < 2; h2++) {
            int m = m0 + warp_m * 32 + mt * 16 + (lane >> 2) + h2 * 8;
            if (m >= M) continue;
#pragma unroll
            for (int nt = 0; nt < 8; nt++) {
                int col = warp_n * 64 + nt * 8 + (lane & 3) * 2;
                float v0 = (acc[mt][nt][h2 * 2]     + __ldg(&bias[col]))     * scale;
                float v1 = (acc[mt][nt][h2 * 2 + 1] + __ldg(&bias[col + 1])) * scale;
                if (Cf) {
                    *(float2*)&Cf[(size_t)m * DIM + col] = make_float2(v0, v1);
                } else {
                    *(__half2*)&Ch[(size_t)m * DIM + col] = __floats2half2_rn(v0, v1);
                }
            }
        }
}

// ---------------------------------------------------------------------------
// Fused FFN: out = LN( h + relu(h@Wf1+bf1)@Wf2 + bf2 ; g2,b2 )
// ---------------------------------------------------------------------------
#define FFN_SMEM_FLOATS (2 * 128 * 132 + 2 * 16 * 136)

__global__ void __launch_bounds__(256)
ffn_fused_kernel(const float* __restrict__ A, const float* __restrict__ Wf1,
                 const float* __restrict__ bf1, const float* __restrict__ Wf2,
                 const float* __restrict__ bf2, float* __restrict__ C,
                 const float* __restrict__ gamma, const float* __restrict__ betap,
                 int M)
{
    extern __shared__ float sm[];
    float (*H)[132] = (float(*)[132])sm;
    float (*T)[132] = (float(*)[132])(sm + 128 * 132);
    float (*Bs)[16][136] = (float(*)[16][136])(sm + 2 * 128 * 132);

    const int tid = threadIdx.x;
    const int lane = tid & 31;
    const int wid = tid >> 5;
    const int warp_m = wid & 3;
    const int warp_n = wid >> 2;
    const int m0 = blockIdx.x * 128;

#pragma unroll
    for (int t = 0; t < 16; t++) {
        int j = tid + t * 256;
        int r = j >> 5, c4 = (j & 31) * 4;
        float4 v = (m0 + r < M) ? *(const float4*)&A[(size_t)(m0 + r) * DIM + c4]
                                : make_float4(0.f, 0.f, 0.f, 0.f);
        H[r][c4 + 0] = to_tf32(v.x);
        H[r][c4 + 1] = to_tf32(v.y);
        H[r][c4 + 2] = to_tf32(v.z);
        H[r][c4 + 3] = to_tf32(v.w);
    }
    __syncthreads();

    float acc2[2][8][4];
#pragma unroll
    for (int i = 0; i < 2; i++)
#pragma unroll
        for (int j = 0; j < 8; j++)
#pragma unroll
            for (int c = 0; c < 4; c++) acc2[i][j][c] = 0.f;

    float4 pbv[2];

#define LOADB1(CH_, T0)                                                       \
    {                                                                         \
        _Pragma("unroll")                                                     \
        for (int _t = 0; _t < 2; _t++) {                                      \
            int j = tid + _t * 256;                                           \
            int br = j >> 5, c4 = (j & 31) * 4;                               \
            pbv[_t] = *(const float4*)&Wf1[(size_t)((T0) * 16 + br) * 512     \
                                           + (CH_) * 128 + c4];               \
        }                                                                     \
    }
#define LOADB2(CH_, T0)                                                       \
    {                                                                         \
        _Pragma("unroll")                                                     \
        for (int _t = 0; _t < 2; _t++) {                                      \
            int j = tid + _t * 256;                                           \
            int br = j >> 5, c4 = (j & 31) * 4;                               \
            pbv[_t] = *(const float4*)&Wf2[(size_t)((CH_) * 128 + (T0) * 16 + br) * 128 + c4]; \
        }                                                                     \
    }
#define STOREB(BUF)                                                           \
    {                                                                         \
        const int buf_ = (BUF);                                               \
        _Pragma("unroll")                                                     \
        for (int _t = 0; _t < 2; _t++) {                                      \
            int j = tid + _t * 256;                                           \
            int br = j >> 5, c4 = (j & 31) * 4;                               \
            Bs[buf_][br][c4 + 0] = to_tf32(pbv[_t].x);                        \
            Bs[buf_][br][c4 + 1] = to_tf32(pbv[_t].y);                        \
            Bs[buf_][br][c4 + 2] = to_tf32(pbv[_t].z);                        \
            Bs[buf_][br][c4 + 3] = to_tf32(pbv[_t].w);                        \
        }                                                                     \
    }

#define GEMM_STEP(ACC, ASRC, B_, KGLOB)                                       \
    {                                                                         \
        _Pragma("unroll")                                                     \
        for (int kk0 = 0; kk0 < 16; kk0 += 8) {                               \
            int kk = (KGLOB) + kk0;                                           \
            unsigned bf[8][2];                                                \
            _Pragma("unroll")                                                 \
            for (int nt = 0; nt < 8; nt++) {                                  \
                int n = warp_n * 64 + nt * 8 + (lane >> 2);                   \
                bf[nt][0] = __float_as_uint(Bs[B_][kk0 + (lane & 3)][n]);     \
                bf[nt][1] = __float_as_uint(Bs[B_][kk0 + 4 + (lane & 3)][n]); \
            }                                                                 \
            _Pragma("unroll")                                                 \
            for (int mt = 0; mt < 2; mt++) {                                  \
                int r0 = warp_m * 32 + mt * 16 + (lane >> 2);                 \
                unsigned a0 = __float_as_uint(ASRC[r0][kk + (lane & 3)]);     \
                unsigned a1 = __float_as_uint(ASRC[r0 + 8][kk + (lane & 3)]); \
                unsigned a2 = __float_as_uint(ASRC[r0][kk + 4 + (lane & 3)]); \
                unsigned a3 = __float_as_uint(ASRC[r0 + 8][kk + 4 + (lane & 3)]); \
                _Pragma("unroll")                                             \
                for (int nt = 0; nt < 8; nt++)                                \
                    mma_tf32(ACC[mt][nt], a0, a1, a2, a3, bf[nt][0], bf[nt][1]); \
            }                                                                 \
        }                                                                     \
    }

#pragma unroll 1
    for (int c = 0; c < 4; c++) {
        float acc1[2][8][4];
#pragma unroll
        for (int i = 0; i < 2; i++)
#pragma unroll
            for (int j = 0; j < 8; j++)
#pragma unroll
                for (int cc = 0; cc < 4; cc++) acc1[i][j][cc] = 0.f;

        LOADB1(c, 0);
        STOREB(0);
        __syncthreads();
#pragma unroll
        for (int t = 0; t < 8; t++) {
            if (t < 7) LOADB1(c, t + 1);
            GEMM_STEP(acc1, H, t & 1, t * 16);
            if (t < 7) STOREB((t + 1) & 1);
            __syncthreads();
        }

#pragma unroll
        for (int mt = 0; mt < 2; mt++)
#pragma unroll
            for (int h2 = 0; h2 < 2; h2++) {
                int row = warp_m * 32 + mt * 16 + (lane >> 2) + h2 * 8;
#pragma unroll
                for (int nt = 0; nt < 8; nt++) {
                    int col = warp_n * 64 + nt * 8 + (lane & 3) * 2;
                    int gcol = c * 128 + col;
                    float t0 = fmaxf(acc1[mt][nt][h2 * 2]     + __ldg(&bf1[gcol]), 0.f);
                    float t1 = fmaxf(acc1[mt][nt][h2 * 2 + 1] + __ldg(&bf1[gcol + 1]), 0.f);
                    T[row][col]     = to_tf32(t0);
                    T[row][col + 1] = to_tf32(t1);
                }
            }

        LOADB2(c, 0);
        STOREB(0);
        __syncthreads();
#pragma unroll
        for (int t = 0; t < 8; t++) {
            if (t < 7) LOADB2(c, t + 1);
            GEMM_STEP(acc2, T, t & 1, t * 16);
            if (t < 7) STOREB((t + 1) & 1);
            __syncthreads();
        }
    }
#undef LOADB1
#undef LOADB2
#undef STOREB
#undef GEMM_STEP

    float (*pr)[2] = (float(*)[2])H;
    float mu[2][2];
#pragma unroll
    for (int mt = 0; mt < 2; mt++)
#pragma unroll
        for (int h2 = 0; h2 < 2; h2++) {
            int row = warp_m * 32 + mt * 16 + (lane >> 2) + h2 * 8;
            int m = m0 + row;
            float s = 0.f;
#pragma unroll
            for (int nt = 0; nt < 8; nt++) {
                int col = warp_n * 64 + nt * 8 + (lane & 3) * 2;
                float r0 = (m < M) ? __ldg(&A[(size_t)m * DIM + col])     : 0.f;
                float r1 = (m < M) ? __ldg(&A[(size_t)m * DIM + col + 1]) : 0.f;
                float t0 = acc2[mt][nt][h2 * 2]     + __ldg(&bf2[col])     + r0;
                float t1 = acc2[mt][nt][h2 * 2 + 1] + __ldg(&bf2[col + 1]) + r1;
                acc2[mt][nt][h2 * 2] = t0;
                acc2[mt][nt][h2 * 2 + 1] = t1;
                s += t0 + t1;
            }
            s += __shfl_xor_sync(0xffffffffu, s, 1);
            s += __shfl_xor_sync(0xffffffffu, s, 2);
            if ((lane & 3) == 0) pr[row][warp_n] = s;
        }
    __syncthreads();
#pragma unroll
    for (int mt = 0; mt < 2; mt++)
#pragma unroll
        for (int h2 = 0; h2 < 2; h2++) {
            int row = warp_m * 32 + mt * 16 + (lane >> 2) + h2 * 8;
            mu[mt][h2] = (pr[row][0] + pr[row][1]) * (1.0f / 128.0f);
        }
    __syncthreads();
#pragma unroll
    for (int mt = 0; mt < 2; mt++)
#pragma unroll
        for (int h2 = 0; h2 < 2; h2++) {
            int row = warp_m * 32 + mt * 16 + (lane >> 2) + h2 * 8;
            float vs = 0.f;
#pragma unroll
            for (int nt = 0; nt < 8; nt++) {
                float d0 = acc2[mt][nt][h2 * 2]     - mu[mt][h2];
                float d1 = acc2[mt][nt][h2 * 2 + 1] - mu[mt][h2];
                vs += d0 * d0 + d1 * d1;
            }
            vs += __shfl_xor_sync(0xffffffffu, vs, 1);
            vs += __shfl_xor_sync(0xffffffffu, vs, 2);
            if ((lane & 3) == 0) pr[row][warp_n] = vs;
        }
    __syncthreads();
#pragma unroll
    for (int mt = 0; mt < 2; mt++)
#pragma unroll
        for (int h2 = 0; h2 < 2; h2++) {
            int row = warp_m * 32 + mt * 16 + (lane >> 2) + h2 * 8;
            int m = m0 + row;
            if (m >= M) continue;
            float var = (pr[row][0] + pr[row][1]) * (1.0f / 128.0f);
            float inv = rsqrtf(var + 1e-5f);
#pragma unroll
            for (int nt = 0; nt < 8; nt++) {
                int col = warp_n * 64 + nt * 8 + (lane & 3) * 2;
                float2 st;
                st.x = (acc2[mt][nt][h2 * 2]     - mu[mt][h2]) * inv * __ldg(&gamma[col])     + __ldg(&betap[col]);
                st.y = (acc2[mt][nt][h2 * 2 + 1] - mu[mt][h2]) * inv * __ldg(&gamma[col + 1]) + __ldg(&betap[col + 1]);
                *(float2*)&C[(size_t)m * DIM + col] = st;
            }
        }
}

// ---------------------------------------------------------------------------
// qwe precompute
// ---------------------------------------------------------------------------
__global__ void __launch_bounds__(256)
qwe_kernel(const float* __restrict__ We, const float* __restrict__ be, int N)
{
    __shared__ float sWe[EDIM * DIM];
    __shared__ float sq[4][DIM];
    __shared__ float sbe[DIM];
    int tid = threadIdx.x;
    for (int i = tid; i < EDIM * DIM; i += 256) sWe[i] = We[i];
    if (tid < DIM) sbe[tid] = be[tid];
    int n0 = blockIdx.x * 4;
    for (int i = tid; i < 4 * DIM; i += 256) {
        int nn = i >> 7, c = i & 127;
        sq[nn][c] = (n0 + nn < N) ? g_q[(size_t)(n0 + nn) * DIM + c] : 0.f;
    }
    __syncthreads();
    int nn = tid >> 6, r = tid & 63, h = r >> 4, i = r & 15;
    int n = n0 + nn;
    if (n >= N) return;
    float a = 0.f;
#pragma unroll
    for (int c = 0; c < 32; c++)
        a = fmaf(sq[nn][h * 32 + c], sWe[i * DIM + h * 32 + c], a);
    g_qwe[(size_t)n * 64 + h * 16 + i] = a;
    if (i == 0) {
        float qb = 0.f;
#pragma unroll
        for (int c = 0; c < 32; c++)
            qb = fmaf(sq[nn][h * 32 + c], sbe[h * 32 + c], qb);
        g_qbe[n * 4 + h] = qb;
    }
}

// ---------------------------------------------------------------------------
// Warp-per-node attention: fp16 k/v/eattr gathers, dynamic queue, 4-edge pipe.
// ---------------------------------------------------------------------------
__device__ __forceinline__ void ld_kv4(const __half* base, int node, int ch0,
                                       float4& out) {
    uint2 raw = *(const uint2*)&base[(size_t)node * DIM + ch0];
    float2 a = __half22float2(*(__half2*)&raw.x);
    float2 b = __half22float2(*(__half2*)&raw.y);
    out = make_float4(a.x, a.y, b.x, b.y);
}

__global__ void __launch_bounds__(256)
node_attn_kernel(const float* __restrict__ We, const float* __restrict__ be,
                 const float* __restrict__ x,  const float* __restrict__ Wbeta,
                 const float* __restrict__ g1, const float* __restrict__ b1,
                 int N)
{
    __shared__ float sWe[EDIM][DIM];
    __shared__ float sbe[DIM];
    for (int i = threadIdx.x; i < EDIM * DIM; i += 256)
        ((float*)sWe)[i] = We[i];
    if (threadIdx.x < DIM) sbe[threadIdx.x] = be[threadIdx.x];
    __syncthreads();

    const int lane = threadIdx.x & 31;
    const int g = lane >> 3;
    const int l8 = lane & 7;
    const int ch0 = g * 32 + l8 * 4;

    for (;;) {
        int n;
        if (lane == 0) n = atomicAdd(&g_work, 1);
        n = __shfl_sync(0xffffffffu, n, 0);
        if (n >= N) break;

        float4 q4 = *(const float4*)&g_q[(size_t)n * DIM + ch0];
        float2 qwe2 = *(const float2*)&g_qwe[(size_t)n * 64 + g * 16 + 2 * l8];
        float qbe = g_qbe[n * 4 + g];

        float4 acc = make_float4(0.f, 0.f, 0.f, 0.f);
        float s0 = 0.f, s1 = 0.f, den = 0.f;

        int beg = g_rowptr[n], end = g_rowptr[n + 1];
        int p = beg;
        for (; p + 4 <= end; p += 4) {
            int sA = __ldg(&g_ssrc[p]);
            int sB = __ldg(&g_ssrc[p + 1]);
            int sC = __ldg(&g_ssrc[p + 2]);
            int sD = __ldg(&g_ssrc[p + 3]);
            float4 kA, kB, kC, kD, vA, vB, vC, vD;
            ld_kv4(g_kh, sA, ch0, kA);
            ld_kv4(g_kh, sB, ch0, kB);
            ld_kv4(g_kh, sC, ch0, kC);
            ld_kv4(g_kh, sD, ch0, kD);
            ld_kv4(g_vh, sA, ch0, vA);
            ld_kv4(g_vh, sB, ch0, vB);
            ld_kv4(g_vh, sC, ch0, vC);
            ld_kv4(g_vh, sD, ch0, vD);
            float2 aA = __half22float2(*(const __half2*)&g_eph[(size_t)p * EDIM + 2 * l8]);
            float2 aB = __half22float2(*(const __half2*)&g_eph[(size_t)(p + 1) * EDIM + 2 * l8]);
            float2 aC = __half22float2(*(const __half2*)&g_eph[(size_t)(p + 2) * EDIM + 2 * l8]);
            float2 aD = __half22float2(*(const __half2*)&g_eph[(size_t)(p + 3) * EDIM + 2 * l8]);

            float pA = q4.x * kA.x + q4.y * kA.y + q4.z * kA.z + q4.w * kA.w
                     + aA.x * qwe2.x + aA.y * qwe2.y;
            float pB = q4.x * kB.x + q4.y * kB.y + q4.z * kB.z + q4.w * kB.w
                     + aB.x * qwe2.x + aB.y * qwe2.y;
            float pC = q4.x * kC.x + q4.y * kC.y + q4.z * kC.z + q4.w * kC.w
                     + aC.x * qwe2.x + aC.y * qwe2.y;
            float pD = q4.x * kD.x + q4.y * kD.y + q4.z * kD.z + q4.w * kD.w
                     + aD.x * qwe2.x + aD.y * qwe2.y;
            pA += __shfl_xor_sync(0xffffffffu, pA, 1);
            pB += __shfl_xor_sync(0xffffffffu, pB, 1);
            pC += __shfl_xor_sync(0xffffffffu, pC, 1);
            pD += __shfl_xor_sync(0xffffffffu, pD, 1);
            pA += __shfl_xor_sync(0xffffffffu, pA, 2);
            pB += __shfl_xor_sync(0xffffffffu, pB, 2);
            pC += __shfl_xor_sync(0xffffffffu, pC, 2);
            pD += __shfl_xor_sync(0xffffffffu, pD, 2);
            pA += __shfl_xor_sync(0xffffffffu, pA, 4);
            pB += __shfl_xor_sync(0xffffffffu, pB, 4);
            pC += __shfl_xor_sync(0xffffffffu, pC, 4);
            pD += __shfl_xor_sync(0xffffffffu, pD, 4);
            float eA = __expf(pA + qbe);
            float eB = __expf(pB + qbe);
            float eC = __expf(pC + qbe);
            float eD = __expf(pD + qbe);
            den += eA;
            acc.x = fmaf(eA, vA.x, acc.x); acc.y = fmaf(eA, vA.y, acc.y);
            acc.z = fmaf(eA, vA.z, acc.z); acc.w = fmaf(eA, vA.w, acc.w);
            s0 = fmaf(eA, aA.x, s0); s1 = fmaf(eA, aA.y, s1);
            den += eB;
            acc.x = fmaf(eB, vB.x, acc.x); acc.y = fmaf(eB, vB.y, acc.y);
            acc.z = fmaf(eB, vB.z, acc.z); acc.w = fmaf(eB, vB.w, acc.w);
            s0 = fmaf(eB, aB.x, s0); s1 = fmaf(eB, aB.y, s1);
            den += eC;
            acc.x = fmaf(eC, vC.x, acc.x); acc.y = fmaf(eC, vC.y, acc.y);
            acc.z = fmaf(eC, vC.z, acc.z); acc.w = fmaf(eC, vC.w, acc.w);
            s0 = fmaf(eC, aC.x, s0); s1 = fmaf(eC, aC.y, s1);
            den += eD;
            acc.x = fmaf(eD, vD.x, acc.x); acc.y = fmaf(eD, vD.y, acc.y);
            acc.z = fmaf(eD, vD.z, acc.z); acc.w = fmaf(eD, vD.w, acc.w);
            s0 = fmaf(eD, aD.x, s0); s1 = fmaf(eD, aD.y, s1);
        }
        for (; p < end; p++) {
            int sA = __ldg(&g_ssrc[p]);
            float2 aA = __half22float2(*(const __half2*)&g_eph[(size_t)p * EDIM + 2 * l8]);
            float4 kA, vA;
            ld_kv4(g_kh, sA, ch0, kA);
            ld_kv4(g_vh, sA, ch0, vA);
            float pp = q4.x * kA.x + q4.y * kA.y + q4.z * kA.z + q4.w * kA.w
                     + aA.x * qwe2.x + aA.y * qwe2.y;
            pp += __shfl_xor_sync(0xffffffffu, pp, 1);
            pp += __shfl_xor_sync(0xffffffffu, pp, 2);
            pp += __shfl_xor_sync(0xffffffffu, pp, 4);
            float ea = __expf(pp + qbe);
            den += ea;
            acc.x = fmaf(ea, vA.x, acc.x); acc.y = fmaf(ea, vA.y, acc.y);
            acc.z = fmaf(ea, vA.z, acc.z); acc.w = fmaf(ea, vA.w, acc.w);
            s0 = fmaf(ea, aA.x, s0); s1 = fmaf(ea, aA.y, s1);
        }

        float4 ev;
        ev.x = den * sbe[ch0];
        ev.y = den * sbe[ch0 + 1];
        ev.z = den * sbe[ch0 + 2];
        ev.w = den * sbe[ch0 + 3];
#pragma unroll
        for (int jj = 0; jj < 8; jj++) {
            int srcl = (g << 3) | jj;
            float sj0 = __shfl_sync(0xffffffffu, s0, srcl);
            float sj1 = __shfl_sync(0xffffffffu, s1, srcl);
            float4 w0 = *(const float4*)&sWe[2 * jj][ch0];
            float4 w1 = *(const float4*)&sWe[2 * jj + 1][ch0];
            ev.x += sj0 * w0.x + sj1 * w1.x;
            ev.y += sj0 * w0.y + sj1 * w1.y;
            ev.z += sj0 * w0.z + sj1 * w1.z;
            ev.w += sj0 * w0.w + sj1 * w1.w;
        }
        float rden = 1.0f / (den + 1e-16f);
        float o[4] = {(acc.x + ev.x) * rden, (acc.y + ev.y) * rden,
                      (acc.z + ev.z) * rden, (acc.w + ev.w) * rden};

        float4 xr4 = *(const float4*)&g_xr[(size_t)n * DIM + ch0];
        float4 wb0 = *(const float4*)&Wbeta[ch0];
        float4 wb1 = *(const float4*)&Wbeta[DIM + ch0];
        float4 wb2 = *(const float4*)&Wbeta[2 * DIM + ch0];
        float xr[4] = {xr4.x, xr4.y, xr4.z, xr4.w};
        float z = wb0.x * o[0] + wb1.x * xr[0] + wb2.x * (o[0] - xr[0])
                + wb0.y * o[1] + wb1.y * xr[1] + wb2.y * (o[1] - xr[1])
                + wb0.z * o[2] + wb1.z * xr[2] + wb2.z * (o[2] - xr[2])
                + wb0.w * o[3] + wb1.w * xr[3] + wb2.w * (o[3] - xr[3]);
        z = warpSum(z);
        float beta = 1.0f / (1.0f + __expf(-z));

        float4 xv = *(const float4*)&x[(size_t)n * DIM + ch0];
        float xx[4] = {xv.x, xv.y, xv.z, xv.w};
        float tv[4], ts = 0.f;
#pragma unroll
        for (int c = 0; c < 4; c++) {
            tv[c] = xx[c] + beta * xr[c] + (1.0f - beta) * o[c];
            ts += tv[c];
        }
        float mu = warpSum(ts) * (1.0f / 128.0f);
        float vs = 0.f;
#pragma unroll
        for (int c = 0; c < 4; c++) { tv[c] -= mu; vs += tv[c] * tv[c]; }
        float var = warpSum(vs) * (1.0f / 128.0f);
        float inv = rsqrtf(var + 1e-5f);

        float4 gg = *(const float4*)&g1[ch0];
        float4 bb = *(const float4*)&b1[ch0];
        float4 st;
        st.x = tv[0] * inv * gg.x + bb.x;
        st.y = tv[1] * inv * gg.y + bb.y;
        st.z = tv[2] * inv * gg.z + bb.z;
        st.w = tv[3] * inv * gg.w + bb.w;
        *(float4*)&g_h[(size_t)n * DIM + ch0] = st;
    }
}

// ---------------------------------------------------------------------------
// Launch: explicit non-blocking streams for both branches.
// ---------------------------------------------------------------------------
extern "C" void kernel_launch(void* const* d_in, const int* in_sizes, int n_in,
                              void* d_out, int out_size)
{
    const float* x      = (const float*)d_in[0];
    const void*  eidx   = d_in[1];
    const float* eattr  = (const float*)d_in[2];
    const float* Wq     = (const float*)d_in[3];
    const float* bq     = (const float*)d_in[4];
    const float* Wk     = (const float*)d_in[5];
    const float* bk     = (const float*)d_in[6];
    const float* Wv     = (const float*)d_in[7];
    const float* bv     = (const float*)d_in[8];
    const float* We     = (const float*)d_in[9];
    const float* be     = (const float*)d_in[10];
    const float* Ws     = (const float*)d_in[11];
    const float* bs     = (const float*)d_in[12];
    const float* Wbeta  = (const float*)d_in[13];
    const float* g1     = (const float*)d_in[14];
    const float* b1     = (const float*)d_in[15];
    const float* Wf1    = (const float*)d_in[16];
    const float* bf1    = (const float*)d_in[17];
    const float* Wf2    = (const float*)d_in[18];
    const float* bf2    = (const float*)d_in[19];
    const float* g2     = (const float*)d_in[20];
    const float* b2     = (const float*)d_in[21];

    const int N = in_sizes[0] / DIM;
    const int E = in_sizes[1] / 2;

    float *h;
    int *cnt, *work;
    cudaGetSymbolAddress((void**)&h, g_h);
    cudaGetSymbolAddress((void**)&cnt, g_cnt);
    cudaGetSymbolAddress((void**)&work, g_work);

    static cudaStream_t s1 = nullptr, s2 = nullptr;
    static cudaEvent_t evFork = nullptr, evCsr = nullptr, evProj = nullptr;
    if (!s1) {
        cudaStreamCreateWithFlags(&s1, cudaStreamNonBlocking);
        cudaStreamCreateWithFlags(&s2, cudaStreamNonBlocking);
        cudaEventCreateWithFlags(&evFork, cudaEventDisableTiming);
        cudaEventCreateWithFlags(&evCsr, cudaEventDisableTiming);
        cudaEventCreateWithFlags(&evProj, cudaEventDisableTiming);
        cudaFuncSetAttribute(ffn_fused_kernel,
                             cudaFuncAttributeMaxDynamicSharedMemorySize,
                             FFN_SMEM_FLOATS * 4);
    }

    const int nb = (N + 1023) / 1024;
    const int gm = (N + 127) / 128;

    // fork from caller stream 0
    cudaEventRecord(evFork, 0);
    cudaStreamWaitEvent(s1, evFork, 0);
    cudaStreamWaitEvent(s2, evFork, 0);

    // branch 1 (s1): CSR chain
    cudaMemsetAsync(cnt, 0, (size_t)N * sizeof(int), s1);
    detect_idx_kernel<<<1, 32, 0, s1>>>((const int*)eidx);
    convert_idx_kernel<<<(E + 255) / 256, 256, 0, s1>>>(eidx, E);
    scanA_kernel<<<nb, 1024, 0, s1>>>(N);
    scanB_kernel<<<1, 32, 0, s1>>>(nb, N, E);
    scanC_kernel<<<nb, 1024, 0, s1>>>(N);
    scatter_kernel<<<(E + 255) / 256, 256, 0, s1>>>(E);
    permute_eattr_kernel<<<(E * 4 + 255) / 256, 256, 0, s1>>>(eattr, E);
    cudaEventRecord(evCsr, s1);

    // branch 2 (s2): projections + qwe + work-counter reset
    cudaMemsetAsync(work, 0, sizeof(int), s2);
    dim3 gproj(gm, 4);
    proj_mma_kernel<<<gproj, 256, 0, s2>>>(x, Wq, bq, Wk, bk, Wv, bv, Ws, bs, N);
    qwe_kernel<<<(N + 3) / 4, 256, 0, s2>>>(We, be, N);
    cudaEventRecord(evProj, s2);

    // join into stream 0
    cudaStreamWaitEvent(0, evCsr, 0);
    cudaStreamWaitEvent(0, evProj, 0);

    node_attn_kernel<<<1184, 256>>>(We, be, x, Wbeta, g1, b1, N);

    ffn_fused_kernel<<<gm, 256, FFN_SMEM_FLOATS * 4>>>(
        h, Wf1, bf1, Wf2, bf2, (float*)d_out, g2, b2, N);
}

// round 14
// speedup vs baseline: 1.2091x; 1.0383x over previous
#include <cuda_runtime.h>
#include <cuda_bf16.h>
#include <cuda_fp16.h>
#include <math.h>

#define NMAX 50000
#define EMAX 800000
#define DIM  128
#define HEADS 4
#define CH   32
#define EDIM 16
#define QSCALE 0.17677669529663687f   // 1/sqrt(32)

// ---------------------------------------------------------------------------
// Scratch
// ---------------------------------------------------------------------------
__device__ float  g_q[NMAX * DIM];
__device__ __half g_kh[NMAX * DIM];
__device__ __half g_vh[NMAX * DIM];
__device__ float  g_xr[NMAX * DIM];
__device__ float  g_h[NMAX * DIM];
__device__ float  g_qwe[(size_t)NMAX * 64];
__device__ float  g_qbe[NMAX * 4];
__device__ __half g_eph[(size_t)EMAX * EDIM];
__device__ int    g_src[EMAX];
__device__ int    g_dst[EMAX];
__device__ int    g_ssrc[EMAX];
__device__ int    g_eid[EMAX];
__device__ int    g_cnt[NMAX];
__device__ int    g_rowptr[NMAX + 1];
__device__ int    g_woff[NMAX];
__device__ int    g_bsum[64];
__device__ int    g_boff[64];
__device__ int    g_idx64;
__device__ int    g_work;

// ---------------------------------------------------------------------------
// Helpers
// ---------------------------------------------------------------------------
__device__ __forceinline__ float warpSum(float v) {
#pragma unroll
    for (int off = 16; off; off >>= 1)
        v += __shfl_xor_sync(0xffffffffu, v, off);
    return v;
}

// fp16 HMMA m16n8k16, fp32 accumulate. C layout identical to tf32 m16n8k8.
__device__ __forceinline__ void mma_f16(float c[4],
                                        unsigned a0, unsigned a1, unsigned a2, unsigned a3,
                                        unsigned b0, unsigned b1) {
    asm volatile(
        "mma.sync.aligned.m16n8k16.row.col.f32.f16.f16.f32 "
        "{%0,%1,%2,%3},{%4,%5,%6,%7},{%8,%9},{%0,%1,%2,%3};"
        : "+f"(c[0]), "+f"(c[1]), "+f"(c[2]), "+f"(c[3])
        : "r"(a0), "r"(a1), "r"(a2), "r"(a3), "r"(b0), "r"(b1));
}

// ---------------------------------------------------------------------------
// Index detect / convert (+fused histogram)
// ---------------------------------------------------------------------------
__global__ void detect_idx_kernel(const int* raw) {
    int t = threadIdx.x;
    int hi_nz = 0, lo_nz = 0;
    for (int i = t; i < 256; i += 32) {
        if (raw[2 * i + 1] != 0) hi_nz = 1;
        if (raw[2 * i] != 0) lo_nz = 1;
    }
    unsigned hi = __ballot_sync(0xffffffffu, hi_nz);
    unsigned lo = __ballot_sync(0xffffffffu, lo_nz);
    if (t == 0) g_idx64 = (hi == 0u && lo != 0u) ? 1 : 0;
}

__global__ void convert_idx_kernel(const void* raw, int E) {
    int i = blockIdx.x * blockDim.x + threadIdx.x;
    if (i >= E) return;
    int s, d;
    if (g_idx64) {
        const long long* p = (const long long*)raw;
        s = (int)p[i];
        d = (int)p[E + i];
    } else {
        const int* p = (const int*)raw;
        s = p[i];
        d = p[E + i];
    }
    g_src[i] = s;
    g_dst[i] = d;
    atomicAdd(&g_cnt[d], 1);
}

// ---------------------------------------------------------------------------
// 3-phase exclusive scan
// ---------------------------------------------------------------------------
__global__ void __launch_bounds__(1024)
scanA_kernel(int N) {
    __shared__ int wsum[32];
    int t = threadIdx.x;
    int i = blockIdx.x * 1024 + t;
    int v = (i < N) ? g_cnt[i] : 0;
    int inc = v;
#pragma unroll
    for (int off = 1; off < 32; off <<= 1) {
        int u = __shfl_up_sync(0xffffffffu, inc, off);
        if ((t & 31) >= off) inc += u;
    }
    if ((t & 31) == 31) wsum[t >> 5] = inc;
    __syncthreads();
    if (t < 32) {
        int w = wsum[t];
        int wi = w;
#pragma unroll
        for (int off = 1; off < 32; off <<= 1) {
            int u = __shfl_up_sync(0xffffffffu, wi, off);
            if (t >= off) wi += u;
        }
        wsum[t] = wi - w;
    }
    __syncthreads();
    int exc = inc - v + wsum[t >> 5];
    if (i < N) g_rowptr[i] = exc;
    if (t == 1023) g_bsum[blockIdx.x] = exc + v;
}

__global__ void scanB_kernel(int nb, int N, int E) {
    int lane = threadIdx.x;
    int v0 = (lane < nb) ? g_bsum[lane] : 0;
    int v1 = (32 + lane < nb) ? g_bsum[32 + lane] : 0;
    int i0 = v0, i1 = v1;
#pragma unroll
    for (int off = 1; off < 32; off <<= 1) {
        int u = __shfl_up_sync(0xffffffffu, i0, off);
        if (lane >= off) i0 += u;
        int u2 = __shfl_up_sync(0xffffffffu, i1, off);
        if (lane >= off) i1 += u2;
    }
    int tot0 = __shfl_sync(0xffffffffu, i0, 31);
    i1 += tot0;
    g_boff[lane] = i0 - v0;
    g_boff[32 + lane] = i1 - v1;
    if (lane == 0) g_rowptr[N] = E;
}

__global__ void __launch_bounds__(1024)
scanC_kernel(int N) {
    int i = blockIdx.x * 1024 + threadIdx.x;
    if (i < N) {
        int r = g_rowptr[i] + g_boff[blockIdx.x];
        g_rowptr[i] = r;
        g_woff[i] = r;
    }
}

__global__ void scatter_kernel(int E) {
    int i = blockIdx.x * blockDim.x + threadIdx.x;
    if (i >= E) return;
    int d = g_dst[i];
    int pos = atomicAdd(&g_woff[d], 1);
    g_ssrc[pos] = g_src[i];
    g_eid[pos] = i;
}

__global__ void __launch_bounds__(256)
permute_eattr_kernel(const float* __restrict__ eattr, int E) {
    int i = blockIdx.x * blockDim.x + threadIdx.x;
    if (i >= E * 4) return;
    int p = i >> 2, q = (i & 3) * 4;
    int e = g_eid[p];
    float4 v = *(const float4*)&eattr[(size_t)e * EDIM + q];
    *(__half2*)&g_eph[(size_t)p * EDIM + q]     = __floats2half2_rn(v.x, v.y);
    *(__half2*)&g_eph[(size_t)p * EDIM + q + 2] = __floats2half2_rn(v.z, v.w);
}

// ---------------------------------------------------------------------------
// fp16 MMA core: BK=16 tiles, double-buffered, one sync per tile.
// As: m-major half [2][128][24] (pad 24 -> 12-word rows, conflict-free).
// Bn: n-major half [2][128][26] (transposed at stage; pad 26 -> 13-word rows).
// ---------------------------------------------------------------------------
__device__ __forceinline__ void mma_core_h(
    const float* __restrict__ A, const float* __restrict__ B,
    int M, int K, int Nout, int n_base, int m0,
    float (&acc)[2][8][4], __half (&As)[2][128][24], __half (&Bn)[2][128][26])
{
    const int tid = threadIdx.x;
    const int lane = tid & 31;
    const int wid = tid >> 5;
    const int warp_m = wid & 3;
    const int warp_n = wid >> 2;
    const int lq = lane & 3;          // thread-in-quad
    const int gq = lane >> 2;         // group id

#pragma unroll
    for (int i = 0; i < 2; i++)
#pragma unroll
        for (int j = 0; j < 8; j++)
#pragma unroll
            for (int c = 0; c < 4; c++) acc[i][j][c] = 0.f;

    float4 pa[2], pb[2];

#define LOAD_TILE(K0)                                                         \
    {                                                                         \
        const int k0c_ = (K0);                                                \
        _Pragma("unroll")                                                     \
        for (int _t = 0; _t < 2; _t++) {                                      \
            int j = tid + _t * 256;                                           \
            int r = j >> 2, q = (j & 3) * 4;                                  \
            pa[_t] = (m0 + r < M)                                             \
                ? *(const float4*)&A[(size_t)(m0 + r) * K + k0c_ + q]         \
                : make_float4(0.f, 0.f, 0.f, 0.f);                            \
            int kr = j >> 5, n4 = (j & 31) * 4;                               \
            pb[_t] = *(const float4*)&B[(size_t)(k0c_ + kr) * Nout + n_base + n4]; \
        }                                                                     \
    }

#define STORE_TILE(BUF)                                                       \
    {                                                                         \
        const int buf_ = (BUF);                                               \
        _Pragma("unroll")                                                     \
        for (int _t = 0; _t < 2; _t++) {                                      \
            int j = tid + _t * 256;                                           \
            int r = j >> 2, q = (j & 3) * 4;                                  \
            *(__half2*)&As[buf_][r][q]     = __floats2half2_rn(pa[_t].x, pa[_t].y); \
            *(__half2*)&As[buf_][r][q + 2] = __floats2half2_rn(pa[_t].z, pa[_t].w); \
            int kr = j >> 5, n4 = (j & 31) * 4;                               \
            Bn[buf_][n4 + 0][kr] = __float2half_rn(pb[_t].x);                 \
            Bn[buf_][n4 + 1][kr] = __float2half_rn(pb[_t].y);                 \
            Bn[buf_][n4 + 2][kr] = __float2half_rn(pb[_t].z);                 \
            Bn[buf_][n4 + 3][kr] = __float2half_rn(pb[_t].w);                 \
        }                                                                     \
    }

    LOAD_TILE(0);
    STORE_TILE(0);
    __syncthreads();

    const int T = K >> 4;
#pragma unroll 2
    for (int tt = 0; tt < T; tt++) {
        if (tt + 1 < T) LOAD_TILE((tt + 1) << 4);
        const int b = tt & 1;
        unsigned bf[8][2];
#pragma unroll
        for (int nt = 0; nt < 8; nt++) {
            int n = warp_n * 64 + nt * 8 + gq;
            bf[nt][0] = *(const unsigned*)&Bn[b][n][2 * lq];
            bf[nt][1] = *(const unsigned*)&Bn[b][n][2 * lq + 8];
        }
#pragma unroll
        for (int mt = 0; mt < 2; mt++) {
            int r0 = warp_m * 32 + mt * 16 + gq;
            unsigned a0 = *(const unsigned*)&As[b][r0][2 * lq];
            unsigned a1 = *(const unsigned*)&As[b][r0 + 8][2 * lq];
            unsigned a2 = *(const unsigned*)&As[b][r0][2 * lq + 8];
            unsigned a3 = *(const unsigned*)&As[b][r0 + 8][2 * lq + 8];
#pragma unroll
            for (int nt = 0; nt < 8; nt++)
                mma_f16(acc[mt][nt], a0, a1, a2, a3, bf[nt][0], bf[nt][1]);
        }
        if (tt + 1 < T) STORE_TILE((tt + 1) & 1);
        __syncthreads();
    }
#undef LOAD_TILE
#undef STORE_TILE
}

// ---------------------------------------------------------------------------
// proj4 (q/k/v/skip): fp16 MMA; q,xr stored fp32; k,v stored fp16.
// ---------------------------------------------------------------------------
__global__ void __launch_bounds__(256)
proj_mma_kernel(const float* __restrict__ A,
                const float* __restrict__ Wq, const float* __restrict__ bq,
                const float* __restrict__ Wk, const float* __restrict__ bk,
                const float* __restrict__ Wv, const float* __restrict__ bv,
                const float* __restrict__ Ws, const float* __restrict__ bs,
                int M)
{
    const float* B; const float* bias; float* Cf; __half* Ch; float scale;
    switch (blockIdx.y) {
        case 0: B = Wq; bias = bq; Cf = g_q;  Ch = nullptr; scale = QSCALE; break;
        case 1: B = Wk; bias = bk; Cf = nullptr; Ch = g_kh; scale = 1.f;   break;
        case 2: B = Wv; bias = bv; Cf = nullptr; Ch = g_vh; scale = 1.f;   break;
        default: B = Ws; bias = bs; Cf = g_xr; Ch = nullptr; scale = 1.f;  break;
    }
    __shared__ __half As[2][128][24];
    __shared__ __half Bn[2][128][26];
    float acc[2][8][4];
    const int m0 = blockIdx.x * 128;
    mma_core_h(A, B, M, DIM, DIM, 0, m0, acc, As, Bn);

    const int lane = threadIdx.x & 31;
    const int wid = threadIdx.x >> 5;
    const int warp_m = wid & 3, warp_n = wid >> 2;
#pragma unroll
    for (int mt = 0; mt < 2; mt++)
#pragma unroll
        for (int h2 = 0; h2 < 2; h2++) {
            int m = m0 + warp_m * 32 + mt * 16 + (lane >> 2) + h2 * 8;
            if (m >= M) continue;
#pragma unroll
            for (int nt = 0; nt < 8; nt++) {
                int col = warp_n * 64 + nt * 8 + (lane & 3) * 2;
                float v0 = (acc[mt][nt][h2 * 2]     + __ldg(&bias[col]))     * scale;
                float v1 = (acc[mt][nt][h2 * 2 + 1] + __ldg(&bias[col + 1])) * scale;
                if (Cf) {
                    *(float2*)&Cf[(size_t)m * DIM + col] = make_float2(v0, v1);
                } else {
                    *(__half2*)&Ch[(size_t)m * DIM + col] = __floats2half2_rn(v0, v1);
                }
            }
        }
}

// ---------------------------------------------------------------------------
// Fused FFN (fp16 MMA): out = LN( h + relu(h@Wf1+bf1)@Wf2 + bf2 ; g2,b2 )
// Dynamic smem halves: H[128][152] | T[128][152] | Bn[2][128][26]
// ---------------------------------------------------------------------------
#define FFN_H_STRIDE 152
#define FFN_SMEM_HALVES (2 * 128 * FFN_H_STRIDE + 2 * 128 * 26)

__global__ void __launch_bounds__(256)
ffn_fused_kernel(const float* __restrict__ A, const float* __restrict__ Wf1,
                 const float* __restrict__ bf1, const float* __restrict__ Wf2,
                 const float* __restrict__ bf2, float* __restrict__ C,
                 const float* __restrict__ gamma, const float* __restrict__ betap,
                 int M)
{
    extern __shared__ __half smh[];
    __half (*H)[FFN_H_STRIDE] = (__half(*)[FFN_H_STRIDE])smh;
    __half (*T)[FFN_H_STRIDE] = (__half(*)[FFN_H_STRIDE])(smh + 128 * FFN_H_STRIDE);
    __half (*Bn)[128][26] = (__half(*)[128][26])(smh + 2 * 128 * FFN_H_STRIDE);

    const int tid = threadIdx.x;
    const int lane = tid & 31;
    const int wid = tid >> 5;
    const int warp_m = wid & 3;
    const int warp_n = wid >> 2;
    const int lq = lane & 3;
    const int gq = lane >> 2;
    const int m0 = blockIdx.x * 128;

    // stage full H tile (fp16) once
#pragma unroll
    for (int it = 0; it < 16; it++) {
        int j = tid + it * 256;
        int r = j >> 5, c4 = (j & 31) * 4;
        float4 v = (m0 + r < M) ? *(const float4*)&A[(size_t)(m0 + r) * DIM + c4]
                                : make_float4(0.f, 0.f, 0.f, 0.f);
        *(__half2*)&H[r][c4]     = __floats2half2_rn(v.x, v.y);
        *(__half2*)&H[r][c4 + 2] = __floats2half2_rn(v.z, v.w);
    }
    __syncthreads();

    float acc2[2][8][4];
#pragma unroll
    for (int i = 0; i < 2; i++)
#pragma unroll
        for (int j = 0; j < 8; j++)
#pragma unroll
            for (int c = 0; c < 4; c++) acc2[i][j][c] = 0.f;

    float4 pbv[2];

#define LOADB1(CH_, T0)                                                       \
    {                                                                         \
        _Pragma("unroll")                                                     \
        for (int _t = 0; _t < 2; _t++) {                                      \
            int j = tid + _t * 256;                                           \
            int kr = j >> 5, n4 = (j & 31) * 4;                               \
            pbv[_t] = *(const float4*)&Wf1[(size_t)((T0) * 16 + kr) * 512     \
                                           + (CH_) * 128 + n4];               \
        }                                                                     \
    }
#define LOADB2(CH_, T0)                                                       \
    {                                                                         \
        _Pragma("unroll")                                                     \
        for (int _t = 0; _t < 2; _t++) {                                      \
            int j = tid + _t * 256;                                           \
            int kr = j >> 5, n4 = (j & 31) * 4;                               \
            pbv[_t] = *(const float4*)&Wf2[(size_t)((CH_) * 128 + (T0) * 16 + kr) * 128 + n4]; \
        }                                                                     \
    }
#define STOREB(BUF)                                                           \
    {                                                                         \
        const int buf_ = (BUF);                                               \
        _Pragma("unroll")                                                     \
        for (int _t = 0; _t < 2; _t++) {                                      \
            int j = tid + _t * 256;                                           \
            int kr = j >> 5, n4 = (j & 31) * 4;                               \
            Bn[buf_][n4 + 0][kr] = __float2half_rn(pbv[_t].x);                \
            Bn[buf_][n4 + 1][kr] = __float2half_rn(pbv[_t].y);                \
            Bn[buf_][n4 + 2][kr] = __float2half_rn(pbv[_t].z);                \
            Bn[buf_][n4 + 3][kr] = __float2half_rn(pbv[_t].w);                \
        }                                                                     \
    }

#define GEMM_STEP_H(ACC, ASRC, B_, KGLOB)                                     \
    {                                                                         \
        unsigned bf[8][2];                                                    \
        _Pragma("unroll")                                                     \
        for (int nt = 0; nt < 8; nt++) {                                      \
            int n = warp_n * 64 + nt * 8 + gq;                                \
            bf[nt][0] = *(const unsigned*)&Bn[B_][n][2 * lq];                 \
            bf[nt][1] = *(const unsigned*)&Bn[B_][n][2 * lq + 8];             \
        }                                                                     \
        _Pragma("unroll")                                                     \
        for (int mt = 0; mt < 2; mt++) {                                      \
            int r0 = warp_m * 32 + mt * 16 + gq;                              \
            unsigned a0 = *(const unsigned*)&ASRC[r0][(KGLOB) + 2 * lq];      \
            unsigned a1 = *(const unsigned*)&ASRC[r0 + 8][(KGLOB) + 2 * lq];  \
            unsigned a2 = *(const unsigned*)&ASRC[r0][(KGLOB) + 2 * lq + 8];  \
            unsigned a3 = *(const unsigned*)&ASRC[r0 + 8][(KGLOB) + 2 * lq + 8]; \
            _Pragma("unroll")                                                 \
            for (int nt = 0; nt < 8; nt++)                                    \
                mma_f16(ACC[mt][nt], a0, a1, a2, a3, bf[nt][0], bf[nt][1]);   \
        }                                                                     \
    }

#pragma unroll 1
    for (int c = 0; c < 4; c++) {
        float acc1[2][8][4];
#pragma unroll
        for (int i = 0; i < 2; i++)
#pragma unroll
            for (int j = 0; j < 8; j++)
#pragma unroll
                for (int cc = 0; cc < 4; cc++) acc1[i][j][cc] = 0.f;

        LOADB1(c, 0);
        STOREB(0);
        __syncthreads();
#pragma unroll
        for (int tt = 0; tt < 8; tt++) {
            if (tt < 7) LOADB1(c, tt + 1);
            GEMM_STEP_H(acc1, H, tt & 1, tt * 16);
            if (tt < 7) STOREB((tt + 1) & 1);
            __syncthreads();
        }

#pragma unroll
        for (int mt = 0; mt < 2; mt++)
#pragma unroll
            for (int h2 = 0; h2 < 2; h2++) {
                int row = warp_m * 32 + mt * 16 + (lane >> 2) + h2 * 8;
#pragma unroll
                for (int nt = 0; nt < 8; nt++) {
                    int col = warp_n * 64 + nt * 8 + (lane & 3) * 2;
                    int gcol = c * 128 + col;
                    float t0 = fmaxf(acc1[mt][nt][h2 * 2]     + __ldg(&bf1[gcol]), 0.f);
                    float t1 = fmaxf(acc1[mt][nt][h2 * 2 + 1] + __ldg(&bf1[gcol + 1]), 0.f);
                    *(__half2*)&T[row][col] = __floats2half2_rn(t0, t1);
                }
            }

        LOADB2(c, 0);
        STOREB(0);
        __syncthreads();   // covers T stores too
#pragma unroll
        for (int tt = 0; tt < 8; tt++) {
            if (tt < 7) LOADB2(c, tt + 1);
            GEMM_STEP_H(acc2, T, tt & 1, tt * 16);
            if (tt < 7) STOREB((tt + 1) & 1);
            __syncthreads();
        }
    }
#undef LOADB1
#undef LOADB2
#undef STOREB
#undef GEMM_STEP_H

    // LN epilogue (residual from global A, fp32 exact)
    float (*pr)[2] = (float(*)[2])smh;   // alias over H (done with it)
    float mu[2][2];
#pragma unroll
    for (int mt = 0; mt < 2; mt++)
#pragma unroll
        for (int h2 = 0; h2 < 2; h2++) {
            int row = warp_m * 32 + mt * 16 + (lane >> 2) + h2 * 8;
            int m = m0 + row;
            float s = 0.f;
#pragma unroll
            for (int nt = 0; nt < 8; nt++) {
                int col = warp_n * 64 + nt * 8 + (lane & 3) * 2;
                float r0 = (m < M) ? __ldg(&A[(size_t)m * DIM + col])     : 0.f;
                float r1 = (m < M) ? __ldg(&A[(size_t)m * DIM + col + 1]) : 0.f;
                float t0 = acc2[mt][nt][h2 * 2]     + __ldg(&bf2[col])     + r0;
                float t1 = acc2[mt][nt][h2 * 2 + 1] + __ldg(&bf2[col + 1]) + r1;
                acc2[mt][nt][h2 * 2] = t0;
                acc2[mt][nt][h2 * 2 + 1] = t1;
                s += t0 + t1;
            }
            s += __shfl_xor_sync(0xffffffffu, s, 1);
            s += __shfl_xor_sync(0xffffffffu, s, 2);
            if ((lane & 3) == 0) pr[row][warp_n] = s;
        }
    __syncthreads();
#pragma unroll
    for (int mt = 0; mt < 2; mt++)
#pragma unroll
        for (int h2 = 0; h2 < 2; h2++) {
            int row = warp_m * 32 + mt * 16 + (lane >> 2) + h2 * 8;
            mu[mt][h2] = (pr[row][0] + pr[row][1]) * (1.0f / 128.0f);
        }
    __syncthreads();
#pragma unroll
    for (int mt = 0; mt < 2; mt++)
#pragma unroll
        for (int h2 = 0; h2 < 2; h2++) {
            int row = warp_m * 32 + mt * 16 + (lane >> 2) + h2 * 8;
            float vs = 0.f;
#pragma unroll
            for (int nt = 0; nt < 8; nt++) {
                float d0 = acc2[mt][nt][h2 * 2]     - mu[mt][h2];
                float d1 = acc2[mt][nt][h2 * 2 + 1] - mu[mt][h2];
                vs += d0 * d0 + d1 * d1;
            }
            vs += __shfl_xor_sync(0xffffffffu, vs, 1);
            vs += __shfl_xor_sync(0xffffffffu, vs, 2);
            if ((lane & 3) == 0) pr[row][warp_n] = vs;
        }
    __syncthreads();
#pragma unroll
    for (int mt = 0; mt < 2; mt++)
#pragma unroll
        for (int h2 = 0; h2 < 2; h2++) {
            int row = warp_m * 32 + mt * 16 + (lane >> 2) + h2 * 8;
            int m = m0 + row;
            if (m >= M) continue;
            float var = (pr[row][0] + pr[row][1]) * (1.0f / 128.0f);
            float inv = rsqrtf(var + 1e-5f);
#pragma unroll
            for (int nt = 0; nt < 8; nt++) {
                int col = warp_n * 64 + nt * 8 + (lane & 3) * 2;
                float2 st;
                st.x = (acc2[mt][nt][h2 * 2]     - mu[mt][h2]) * inv * __ldg(&gamma[col])     + __ldg(&betap[col]);
                st.y = (acc2[mt][nt][h2 * 2 + 1] - mu[mt][h2]) * inv * __ldg(&gamma[col + 1]) + __ldg(&betap[col + 1]);
                *(float2*)&C[(size_t)m * DIM + col] = st;
            }
        }
}

// ---------------------------------------------------------------------------
// qwe precompute
// ---------------------------------------------------------------------------
__global__ void __launch_bounds__(256)
qwe_kernel(const float* __restrict__ We, const float* __restrict__ be, int N)
{
    __shared__ float sWe[EDIM * DIM];
    __shared__ float sq[4][DIM];
    __shared__ float sbe[DIM];
    int tid = threadIdx.x;
    for (int i = tid; i < EDIM * DIM; i += 256) sWe[i] = We[i];
    if (tid < DIM) sbe[tid] = be[tid];
    int n0 = blockIdx.x * 4;
    for (int i = tid; i < 4 * DIM; i += 256) {
        int nn = i >> 7, c = i & 127;
        sq[nn][c] = (n0 + nn < N) ? g_q[(size_t)(n0 + nn) * DIM + c] : 0.f;
    }
    __syncthreads();
    int nn = tid >> 6, r = tid & 63, h = r >> 4, i = r & 15;
    int n = n0 + nn;
    if (n >= N) return;
    float a = 0.f;
#pragma unroll
    for (int c = 0; c < 32; c++)
        a = fmaf(sq[nn][h * 32 + c], sWe[i * DIM + h * 32 + c], a);
    g_qwe[(size_t)n * 64 + h * 16 + i] = a;
    if (i == 0) {
        float qb = 0.f;
#pragma unroll
        for (int c = 0; c < 32; c++)
            qb = fmaf(sq[nn][h * 32 + c], sbe[h * 32 + c], qb);
        g_qbe[n * 4 + h] = qb;
    }
}

// ---------------------------------------------------------------------------
// Warp-per-node attention: fp16 k/v/eattr gathers, dynamic queue, 4-edge pipe.
// ---------------------------------------------------------------------------
__device__ __forceinline__ void ld_kv4(const __half* base, int node, int ch0,
                                       float4& out) {
    uint2 raw = *(const uint2*)&base[(size_t)node * DIM + ch0];
    float2 a = __half22float2(*(__half2*)&raw.x);
    float2 b = __half22float2(*(__half2*)&raw.y);
    out = make_float4(a.x, a.y, b.x, b.y);
}

__global__ void __launch_bounds__(256)
node_attn_kernel(const float* __restrict__ We, const float* __restrict__ be,
                 const float* __restrict__ x,  const float* __restrict__ Wbeta,
                 const float* __restrict__ g1, const float* __restrict__ b1,
                 int N)
{
    __shared__ float sWe[EDIM][DIM];
    __shared__ float sbe[DIM];
    for (int i = threadIdx.x; i < EDIM * DIM; i += 256)
        ((float*)sWe)[i] = We[i];
    if (threadIdx.x < DIM) sbe[threadIdx.x] = be[threadIdx.x];
    __syncthreads();

    const int lane = threadIdx.x & 31;
    const int g = lane >> 3;
    const int l8 = lane & 7;
    const int ch0 = g * 32 + l8 * 4;

    for (;;) {
        int n;
        if (lane == 0) n = atomicAdd(&g_work, 1);
        n = __shfl_sync(0xffffffffu, n, 0);
        if (n >= N) break;

        float4 q4 = *(const float4*)&g_q[(size_t)n * DIM + ch0];
        float2 qwe2 = *(const float2*)&g_qwe[(size_t)n * 64 + g * 16 + 2 * l8];
        float qbe = g_qbe[n * 4 + g];

        float4 acc = make_float4(0.f, 0.f, 0.f, 0.f);
        float s0 = 0.f, s1 = 0.f, den = 0.f;

        int beg = g_rowptr[n], end = g_rowptr[n + 1];
        int p = beg;
        for (; p + 4 <= end; p += 4) {
            int sA = __ldg(&g_ssrc[p]);
            int sB = __ldg(&g_ssrc[p + 1]);
            int sC = __ldg(&g_ssrc[p + 2]);
            int sD = __ldg(&g_ssrc[p + 3]);
            float4 kA, kB, kC, kD, vA, vB, vC, vD;
            ld_kv4(g_kh, sA, ch0, kA);
            ld_kv4(g_kh, sB, ch0, kB);
            ld_kv4(g_kh, sC, ch0, kC);
            ld_kv4(g_kh, sD, ch0, kD);
            ld_kv4(g_vh, sA, ch0, vA);
            ld_kv4(g_vh, sB, ch0, vB);
            ld_kv4(g_vh, sC, ch0, vC);
            ld_kv4(g_vh, sD, ch0, vD);
            float2 aA = __half22float2(*(const __half2*)&g_eph[(size_t)p * EDIM + 2 * l8]);
            float2 aB = __half22float2(*(const __half2*)&g_eph[(size_t)(p + 1) * EDIM + 2 * l8]);
            float2 aC = __half22float2(*(const __half2*)&g_eph[(size_t)(p + 2) * EDIM + 2 * l8]);
            float2 aD = __half22float2(*(const __half2*)&g_eph[(size_t)(p + 3) * EDIM + 2 * l8]);

            float pA = q4.x * kA.x + q4.y * kA.y + q4.z * kA.z + q4.w * kA.w
                     + aA.x * qwe2.x + aA.y * qwe2.y;
            float pB = q4.x * kB.x + q4.y * kB.y + q4.z * kB.z + q4.w * kB.w
                     + aB.x * qwe2.x + aB.y * qwe2.y;
            float pC = q4.x * kC.x + q4.y * kC.y + q4.z * kC.z + q4.w * kC.w
                     + aC.x * qwe2.x + aC.y * qwe2.y;
            float pD = q4.x * kD.x + q4.y * kD.y + q4.z * kD.z + q4.w * kD.w
                     + aD.x * qwe2.x + aD.y * qwe2.y;
            pA += __shfl_xor_sync(0xffffffffu, pA, 1);
            pB += __shfl_xor_sync(0xffffffffu, pB, 1);
            pC += __shfl_xor_sync(0xffffffffu, pC, 1);
            pD += __shfl_xor_sync(0xffffffffu, pD, 1);
            pA += __shfl_xor_sync(0xffffffffu, pA, 2);
            pB += __shfl_xor_sync(0xffffffffu, pB, 2);
            pC += __shfl_xor_sync(0xffffffffu, pC, 2);
            pD += __shfl_xor_sync(0xffffffffu, pD, 2);
            pA += __shfl_xor_sync(0xffffffffu, pA, 4);
            pB += __shfl_xor_sync(0xffffffffu, pB, 4);
            pC += __shfl_xor_sync(0xffffffffu, pC, 4);
            pD += __shfl_xor_sync(0xffffffffu, pD, 4);
            float eA = __expf(pA + qbe);
            float eB = __expf(pB + qbe);
            float eC = __expf(pC + qbe);
            float eD = __expf(pD + qbe);
            den += eA;
            acc.x = fmaf(eA, vA.x, acc.x); acc.y = fmaf(eA, vA.y, acc.y);
            acc.z = fmaf(eA, vA.z, acc.z); acc.w = fmaf(eA, vA.w, acc.w);
            s0 = fmaf(eA, aA.x, s0); s1 = fmaf(eA, aA.y, s1);
            den += eB;
            acc.x = fmaf(eB, vB.x, acc.x); acc.y = fmaf(eB, vB.y, acc.y);
            acc.z = fmaf(eB, vB.z, acc.z); acc.w = fmaf(eB, vB.w, acc.w);
            s0 = fmaf(eB, aB.x, s0); s1 = fmaf(eB, aB.y, s1);
            den += eC;
            acc.x = fmaf(eC, vC.x, acc.x); acc.y = fmaf(eC, vC.y, acc.y);
            acc.z = fmaf(eC, vC.z, acc.z); acc.w = fmaf(eC, vC.w, acc.w);
            s0 = fmaf(eC, aC.x, s0); s1 = fmaf(eC, aC.y, s1);
            den += eD;
            acc.x = fmaf(eD, vD.x, acc.x); acc.y = fmaf(eD, vD.y, acc.y);
            acc.z = fmaf(eD, vD.z, acc.z); acc.w = fmaf(eD, vD.w, acc.w);
            s0 = fmaf(eD, aD.x, s0); s1 = fmaf(eD, aD.y, s1);
        }
        for (; p < end; p++) {
            int sA = __ldg(&g_ssrc[p]);
            float2 aA = __half22float2(*(const __half2*)&g_eph[(size_t)p * EDIM + 2 * l8]);
            float4 kA, vA;
            ld_kv4(g_kh, sA, ch0, kA);
            ld_kv4(g_vh, sA, ch0, vA);
            float pp = q4.x * kA.x + q4.y * kA.y + q4.z * kA.z + q4.w * kA.w
                     + aA.x * qwe2.x + aA.y * qwe2.y;
            pp += __shfl_xor_sync(0xffffffffu, pp, 1);
            pp += __shfl_xor_sync(0xffffffffu, pp, 2);
            pp += __shfl_xor_sync(0xffffffffu, pp, 4);
            float ea = __expf(pp + qbe);
            den += ea;
            acc.x = fmaf(ea, vA.x, acc.x); acc.y = fmaf(ea, vA.y, acc.y);
            acc.z = fmaf(ea, vA.z, acc.z); acc.w = fmaf(ea, vA.w, acc.w);
            s0 = fmaf(ea, aA.x, s0); s1 = fmaf(ea, aA.y, s1);
        }

        float4 ev;
        ev.x = den * sbe[ch0];
        ev.y = den * sbe[ch0 + 1];
        ev.z = den * sbe[ch0 + 2];
        ev.w = den * sbe[ch0 + 3];
#pragma unroll
        for (int jj = 0; jj < 8; jj++) {
            int srcl = (g << 3) | jj;
            float sj0 = __shfl_sync(0xffffffffu, s0, srcl);
            float sj1 = __shfl_sync(0xffffffffu, s1, srcl);
            float4 w0 = *(const float4*)&sWe[2 * jj][ch0];
            float4 w1 = *(const float4*)&sWe[2 * jj + 1][ch0];
            ev.x += sj0 * w0.x + sj1 * w1.x;
            ev.y += sj0 * w0.y + sj1 * w1.y;
            ev.z += sj0 * w0.z + sj1 * w1.z;
            ev.w += sj0 * w0.w + sj1 * w1.w;
        }
        float rden = 1.0f / (den + 1e-16f);
        float o[4] = {(acc.x + ev.x) * rden, (acc.y + ev.y) * rden,
                      (acc.z + ev.z) * rden, (acc.w + ev.w) * rden};

        float4 xr4 = *(const float4*)&g_xr[(size_t)n * DIM + ch0];
        float4 wb0 = *(const float4*)&Wbeta[ch0];
        float4 wb1 = *(const float4*)&Wbeta[DIM + ch0];
        float4 wb2 = *(const float4*)&Wbeta[2 * DIM + ch0];
        float xr[4] = {xr4.x, xr4.y, xr4.z, xr4.w};
        float z = wb0.x * o[0] + wb1.x * xr[0] + wb2.x * (o[0] - xr[0])
                + wb0.y * o[1] + wb1.y * xr[1] + wb2.y * (o[1] - xr[1])
                + wb0.z * o[2] + wb1.z * xr[2] + wb2.z * (o[2] - xr[2])
                + wb0.w * o[3] + wb1.w * xr[3] + wb2.w * (o[3] - xr[3]);
        z = warpSum(z);
        float beta = 1.0f / (1.0f + __expf(-z));

        float4 xv = *(const float4*)&x[(size_t)n * DIM + ch0];
        float xx[4] = {xv.x, xv.y, xv.z, xv.w};
        float tv[4], ts = 0.f;
#pragma unroll
        for (int c = 0; c < 4; c++) {
            tv[c] = xx[c] + beta * xr[c] + (1.0f - beta) * o[c];
            ts += tv[c];
        }
        float mu = warpSum(ts) * (1.0f / 128.0f);
        float vs = 0.f;
#pragma unroll
        for (int c = 0; c < 4; c++) { tv[c] -= mu; vs += tv[c] * tv[c]; }
        float var = warpSum(vs) * (1.0f / 128.0f);
        float inv = rsqrtf(var + 1e-5f);

        float4 gg = *(const float4*)&g1[ch0];
        float4 bb = *(const float4*)&b1[ch0];
        float4 st;
        st.x = tv[0] * inv * gg.x + bb.x;
        st.y = tv[1] * inv * gg.y + bb.y;
        st.z = tv[2] * inv * gg.z + bb.z;
        st.w = tv[3] * inv * gg.w + bb.w;
        *(float4*)&g_h[(size_t)n * DIM + ch0] = st;
    }
}

// ---------------------------------------------------------------------------
// Launch: explicit non-blocking streams for both branches.
// ---------------------------------------------------------------------------
extern "C" void kernel_launch(void* const* d_in, const int* in_sizes, int n_in,
                              void* d_out, int out_size)
{
    const float* x      = (const float*)d_in[0];
    const void*  eidx   = d_in[1];
    const float* eattr  = (const float*)d_in[2];
    const float* Wq     = (const float*)d_in[3];
    const float* bq     = (const float*)d_in[4];
    const float* Wk     = (const float*)d_in[5];
    const float* bk     = (const float*)d_in[6];
    const float* Wv     = (const float*)d_in[7];
    const float* bv     = (const float*)d_in[8];
    const float* We     = (const float*)d_in[9];
    const float* be     = (const float*)d_in[10];
    const float* Ws     = (const float*)d_in[11];
    const float* bs     = (const float*)d_in[12];
    const float* Wbeta  = (const float*)d_in[13];
    const float* g1     = (const float*)d_in[14];
    const float* b1     = (const float*)d_in[15];
    const float* Wf1    = (const float*)d_in[16];
    const float* bf1    = (const float*)d_in[17];
    const float* Wf2    = (const float*)d_in[18];
    const float* bf2    = (const float*)d_in[19];
    const float* g2     = (const float*)d_in[20];
    const float* b2     = (const float*)d_in[21];

    const int N = in_sizes[0] / DIM;
    const int E = in_sizes[1] / 2;

    float *h;
    int *cnt, *work;
    cudaGetSymbolAddress((void**)&h, g_h);
    cudaGetSymbolAddress((void**)&cnt, g_cnt);
    cudaGetSymbolAddress((void**)&work, g_work);

    static cudaStream_t s1 = nullptr, s2 = nullptr;
    static cudaEvent_t evFork = nullptr, evCsr = nullptr, evProj = nullptr;
    if (!s1) {
        cudaStreamCreateWithFlags(&s1, cudaStreamNonBlocking);
        cudaStreamCreateWithFlags(&s2, cudaStreamNonBlocking);
        cudaEventCreateWithFlags(&evFork, cudaEventDisableTiming);
        cudaEventCreateWithFlags(&evCsr, cudaEventDisableTiming);
        cudaEventCreateWithFlags(&evProj, cudaEventDisableTiming);
        cudaFuncSetAttribute(ffn_fused_kernel,
                             cudaFuncAttributeMaxDynamicSharedMemorySize,
                             FFN_SMEM_HALVES * 2);
    }

    const int nb = (N + 1023) / 1024;
    const int gm = (N + 127) / 128;

    // fork from caller stream 0
    cudaEventRecord(evFork, 0);
    cudaStreamWaitEvent(s1, evFork, 0);
    cudaStreamWaitEvent(s2, evFork, 0);

    // branch 1 (s1): CSR chain
    cudaMemsetAsync(cnt, 0, (size_t)N * sizeof(int), s1);
    detect_idx_kernel<<<1, 32, 0, s1>>>((const int*)eidx);
    convert_idx_kernel<<<(E + 255) / 256, 256, 0, s1>>>(eidx, E);
    scanA_kernel<<<nb, 1024, 0, s1>>>(N);
    scanB_kernel<<<1, 32, 0, s1>>>(nb, N, E);
    scanC_kernel<<<nb, 1024, 0, s1>>>(N);
    scatter_kernel<<<(E + 255) / 256, 256, 0, s1>>>(E);
    permute_eattr_kernel<<<(E * 4 + 255) / 256, 256, 0, s1>>>(eattr, E);
    cudaEventRecord(evCsr, s1);

    // branch 2 (s2): projections + qwe + work-counter reset
    cudaMemsetAsync(work, 0, sizeof(int), s2);
    dim3 gproj(gm, 4);
    proj_mma_kernel<<<gproj, 256, 0, s2>>>(x, Wq, bq, Wk, bk, Wv, bv, Ws, bs, N);
    qwe_kernel<<<(N + 3) / 4, 256, 0, s2>>>(We, be, N);
    cudaEventRecord(evProj, s2);

    // join into stream 0
    cudaStreamWaitEvent(0, evCsr, 0);
    cudaStreamWaitEvent(0, evProj, 0);

    node_attn_kernel<<<1184, 256>>>(We, be, x, Wbeta, g1, b1, N);

    ffn_fused_kernel<<<gm, 256, FFN_SMEM_HALVES * 2>>>(
        h, Wf1, bf1, Wf2, bf2, (float*)d_out, g2, b2, N);
}